// round 5
// baseline (speedup 1.0000x reference)
#include <cuda_runtime.h>
#include <cuda_bf16.h>
#include <math.h>
#include <stdint.h>

#define TSRC 64
#define BB   64
#define EE   512
#define HH   1024
#define H4   4096
#define VV   32000
#define TD   63

// ---------------- fp32 scratch ----------------
constexpr size_t SZ_X    = (size_t)TSRC*BB*EE;
constexpr size_t SZ_Y    = (size_t)TD*BB*EE;
constexpr size_t SZ_XF   = (size_t)TSRC*BB*H4;
constexpr size_t SZ_YW   = (size_t)TD*BB*H4;
constexpr size_t SZ_OUTH = (size_t)TSRC*BB*HH;
constexpr size_t SZ_ENCH = (size_t)BB*TSRC*2*HH;
constexpr size_t SZ_ENCP = (size_t)BB*TSRC*HH;
constexpr size_t SZ_OUTS = (size_t)TD*BB*HH;
constexpr size_t SZ_BH   = (size_t)BB*HH;
constexpr size_t SZ_CAT2 = (size_t)BB*2*HH;
constexpr size_t SZ_CAT3 = (size_t)BB*3*HH;
constexpr size_t SZ_ACAT = (size_t)BB*2*HH;
constexpr size_t SZ_PART = (size_t)12*BB*H4;
constexpr size_t SZ_BS   = (size_t)3*H4;
constexpr size_t SZ_ROWS = (size_t)4096;
constexpr size_t SZ_PM   = (size_t)250*4096;

constexpr size_t OFF_X    = 0;
constexpr size_t OFF_Y    = OFF_X    + SZ_X;
constexpr size_t OFF_XF   = OFF_Y    + SZ_Y;
constexpr size_t OFF_XB   = OFF_XF   + SZ_XF;
constexpr size_t OFF_YW   = OFF_XB   + SZ_XF;
constexpr size_t OFF_OUTF = OFF_YW   + SZ_YW;
constexpr size_t OFF_OUTB = OFF_OUTF + SZ_OUTH;
constexpr size_t OFF_ENCH = OFF_OUTB + SZ_OUTH;
constexpr size_t OFF_ENCP = OFF_ENCH + SZ_ENCH;
constexpr size_t OFF_OUTS = OFF_ENCP + SZ_ENCP;
constexpr size_t OFF_H    = OFF_OUTS + SZ_OUTS;   // enc fwd h
constexpr size_t OFF_C    = OFF_H    + SZ_BH;     // enc fwd c
constexpr size_t OFF_H0   = OFF_C    + SZ_BH;     // enc bwd h, later dec h
constexpr size_t OFF_C0   = OFF_H0   + SZ_BH;     // enc bwd c, later dec c
constexpr size_t OFF_HCAT = OFF_C0   + SZ_BH;
constexpr size_t OFF_CCAT = OFF_HCAT + SZ_CAT2;
constexpr size_t OFF_ATT  = OFF_CCAT + SZ_CAT2;
constexpr size_t OFF_ACAT = OFF_ATT  + SZ_CAT3;
constexpr size_t OFF_PART = OFF_ACAT + SZ_ACAT;
constexpr size_t OFF_BS   = OFF_PART + SZ_PART;
constexpr size_t OFF_GOLD = OFF_BS   + SZ_BS;
constexpr size_t OFF_LSE  = OFF_GOLD + SZ_ROWS;
constexpr size_t OFF_PMAX = OFF_LSE  + SZ_ROWS;
constexpr size_t OFF_PSUM = OFF_PMAX + SZ_PM;
constexpr size_t TOTAL    = OFF_PSUM + SZ_PM;

__device__ float g_buf[TOTAL];
__device__ unsigned g_cnt[4];   // ticket-barrier counters (stay multiple-of-n across replays)

// ---------------- bf16 scratch ----------------
constexpr size_t BOFF_WVOC = 0;
constexpr size_t BOFF_WHHF = BOFF_WVOC + (size_t)VV*HH;
constexpr size_t BOFF_WHHB = BOFF_WHHF + (size_t)H4*HH;
constexpr size_t BOFF_WCAT = BOFF_WHHB + (size_t)H4*HH;
constexpr size_t BOFF_WIHF = BOFF_WCAT + (size_t)H4*2*HH;
constexpr size_t BOFF_WIHB = BOFF_WIHF + (size_t)H4*EE;
constexpr size_t BOFF_WIHDY= BOFF_WIHB + (size_t)H4*EE;
constexpr size_t BOFF_WATT = BOFF_WIHDY+ (size_t)H4*EE;
constexpr size_t BOFF_WCMB = BOFF_WATT + (size_t)HH*2*HH;
constexpr size_t BTOTAL    = BOFF_WCMB + (size_t)HH*3*HH;

__device__ __nv_bfloat16 g_bf[BTOTAL];

__device__ __forceinline__ float sigm(float x) { return 1.0f / (1.0f + expf(-x)); }

__device__ __forceinline__ uint32_t packbf(float lo, float hi) {
    uint32_t r;
    asm("cvt.rn.bf16x2.f32 %0, %1, %2;" : "=r"(r) : "f"(hi), "f"(lo));
    return r;
}

// grid-wide ticket barrier over n blocks sharing counter c.
__device__ __forceinline__ void gbar(unsigned* c, unsigned n) {
    __syncthreads();
    if (threadIdx.x == 0) {
        __threadfence();
        unsigned my = atomicAdd(c, 1u);
        unsigned target = (my / n + 1u) * n;
        while ((int)(*(volatile unsigned*)c - target) < 0) __nanosleep(64);
        __threadfence();
    }
    __syncthreads();
}

// ---------------- utility kernels ----------------
__global__ void bias3_k(float* bs,
                        const float* __restrict__ a1, const float* __restrict__ a2,
                        const float* __restrict__ b1, const float* __restrict__ b2,
                        const float* __restrict__ c1, const float* __restrict__ c2) {
    int j = blockIdx.x * 256 + threadIdx.x;
    if (j < H4) {
        bs[j]        = a1[j] + a2[j];
        bs[H4 + j]   = b1[j] + b2[j];
        bs[2*H4 + j] = c1[j] + c2[j];
    }
}

__global__ void gather_k(float* __restrict__ out, const float* __restrict__ emb,
                         const int* __restrict__ idx) {
    int row = blockIdx.x;
    int id  = idx[row];
    const float4* s = (const float4*)(emb + (size_t)id * EE);
    float4* d = (float4*)(out + (size_t)row * EE);
    d[threadIdx.x] = s[threadIdx.x];
}

// strided fp32 -> bf16, 8 elems/thread. cols % 8 == 0.
__global__ void cvt_rows(__nv_bfloat16* __restrict__ dst, const float* __restrict__ src,
                         int rows, int cols, int srcStride) {
    size_t n8 = (size_t)rows * cols / 8;
    size_t i = (size_t)blockIdx.x * 256 + threadIdx.x;
    if (i >= n8) return;
    size_t e = i * 8;
    int r = (int)(e / cols), c = (int)(e % cols);
    const float* p = src + (size_t)r * srcStride + c;
    float4 v0 = *(const float4*)p;
    float4 v1 = *(const float4*)(p + 4);
    uint4 o;
    o.x = packbf(v0.x, v0.y); o.y = packbf(v0.z, v0.w);
    o.z = packbf(v1.x, v1.y); o.w = packbf(v1.z, v1.w);
    *(uint4*)(dst + e) = o;
}

// Wcat[n][0:1024] = Whhd[n][:], Wcat[n][1024:2048] = Wihd[n][512:1536]
__global__ void cvt_cat(__nv_bfloat16* __restrict__ dst, const float* __restrict__ whh,
                        const float* __restrict__ wih) {
    size_t i = (size_t)blockIdx.x * 256 + threadIdx.x;   // over H4*2048/8
    if (i >= (size_t)H4 * 2048 / 8) return;
    size_t e = i * 8;
    int n = (int)(e >> 11), j = (int)(e & 2047);
    const float* p = (j < 1024) ? (whh + (size_t)n * HH + j)
                                : (wih + (size_t)n * 1536 + 512 + (j - 1024));
    float4 v0 = *(const float4*)p;
    float4 v1 = *(const float4*)(p + 4);
    uint4 o;
    o.x = packbf(v0.x, v0.y); o.y = packbf(v0.z, v0.w);
    o.z = packbf(v1.x, v1.y); o.w = packbf(v1.z, v1.w);
    *(uint4*)(dst + e) = o;
}

__global__ void ench_k(float* __restrict__ ench, const float* __restrict__ outf,
                       const float* __restrict__ outb) {
    int idx = blockIdx.x * 256 + threadIdx.x;
    int t = idx >> 16;
    int r = idx & 65535;
    int b = r >> 10, j = r & 1023;
    size_t dst = (size_t)b * (TSRC*2*HH) + (size_t)t * 2*HH + j;
    ench[dst]      = outf[idx];
    ench[dst + HH] = outb[idx];
}

__global__ void sumsl_k(float* __restrict__ dst, const float* __restrict__ part, int ns) {
    int idx = blockIdx.x * 256 + threadIdx.x;
    float s = 0.f;
    for (int q = 0; q < ns; q++) s += part[(size_t)q * 65536 + idx];
    dst[idx] = s;
}

// ================= bf16 tensor-core GEMM (big, parallel) =================
#define SASTR 72

template<bool FUSED>
__global__ __launch_bounds__(256)
void bgemm(const float* __restrict__ A, int lda,
           const __nv_bfloat16* __restrict__ B, int ldb,
           float* __restrict__ C, int ldc,
           int M, int K, const float* __restrict__ bias,
           float* __restrict__ pmax, float* __restrict__ psum) {
    __shared__ __align__(16) __nv_bfloat16 As[128 * SASTR];
    __shared__ __align__(16) __nv_bfloat16 Bs[128 * SASTR];
    __shared__ float smx[2][128];
    __shared__ float sms[2][128];

    const int bm = blockIdx.y * 128;
    const int bn = blockIdx.x * 128;
    const int tid  = threadIdx.x;
    const int lane = tid & 31;
    const int wid  = tid >> 5;
    const int wm   = (wid >> 1) * 32;
    const int wn   = (wid & 1) * 64;
    const int g    = lane >> 2;
    const int t    = lane & 3;

    float acc[2][8][4];
    #pragma unroll
    for (int i = 0; i < 2; i++)
        #pragma unroll
        for (int j = 0; j < 8; j++)
            #pragma unroll
            for (int r = 0; r < 4; r++) acc[i][j][r] = 0.f;

    for (int kt = 0; kt < K; kt += 64) {
        #pragma unroll
        for (int q = 0; q < 8; q++) {
            int f = q * 256 + tid;
            int row = f >> 4;
            int c4 = (f & 15) << 2;
            int gr = bm + row;
            float4 v = make_float4(0.f,0.f,0.f,0.f);
            if (gr < M) v = *(const float4*)(A + (size_t)gr * lda + kt + c4);
            *(uint32_t*)&As[row * SASTR + c4]     = packbf(v.x, v.y);
            *(uint32_t*)&As[row * SASTR + c4 + 2] = packbf(v.z, v.w);
        }
        #pragma unroll
        for (int q = 0; q < 4; q++) {
            int f = q * 256 + tid;
            int row = f >> 3;
            int c8 = (f & 7) << 3;
            uint4 v = *(const uint4*)(B + (size_t)(bn + row) * ldb + kt + c8);
            *(uint4*)&Bs[row * SASTR + c8] = v;
        }
        __syncthreads();

        #pragma unroll
        for (int kk = 0; kk < 4; kk++) {
            uint32_t bf[8][2];
            #pragma unroll
            for (int j = 0; j < 8; j++) {
                int rb = (wn + j*8 + g) * SASTR + kk*16;
                bf[j][0] = *(const uint32_t*)&Bs[rb + 2*t];
                bf[j][1] = *(const uint32_t*)&Bs[rb + 8 + 2*t];
            }
            #pragma unroll
            for (int i = 0; i < 2; i++) {
                int ra0 = (wm + i*16 + g) * SASTR + kk*16;
                int ra1 = (wm + i*16 + 8 + g) * SASTR + kk*16;
                uint32_t a0 = *(const uint32_t*)&As[ra0 + 2*t];
                uint32_t a1 = *(const uint32_t*)&As[ra1 + 2*t];
                uint32_t a2 = *(const uint32_t*)&As[ra0 + 8 + 2*t];
                uint32_t a3 = *(const uint32_t*)&As[ra1 + 8 + 2*t];
                #pragma unroll
                for (int j = 0; j < 8; j++) {
                    asm volatile(
                        "mma.sync.aligned.m16n8k16.row.col.f32.bf16.bf16.f32 "
                        "{%0,%1,%2,%3}, {%4,%5,%6,%7}, {%8,%9}, {%0,%1,%2,%3};"
                        : "+f"(acc[i][j][0]), "+f"(acc[i][j][1]),
                          "+f"(acc[i][j][2]), "+f"(acc[i][j][3])
                        : "r"(a0), "r"(a1), "r"(a2), "r"(a3),
                          "r"(bf[j][0]), "r"(bf[j][1]));
                }
            }
        }
        __syncthreads();
    }

    if (!FUSED) {
        #pragma unroll
        for (int i = 0; i < 2; i++) {
            int r0 = bm + wm + i*16 + g;
            int r1 = r0 + 8;
            #pragma unroll
            for (int j = 0; j < 8; j++) {
                int col = bn + wn + j*8 + 2*t;
                float b0 = bias ? bias[col]   : 0.f;
                float b1 = bias ? bias[col+1] : 0.f;
                if (r0 < M) *(float2*)(C + (size_t)r0 * ldc + col) =
                    make_float2(acc[i][j][0] + b0, acc[i][j][1] + b1);
                if (r1 < M) *(float2*)(C + (size_t)r1 * ldc + col) =
                    make_float2(acc[i][j][2] + b0, acc[i][j][3] + b1);
            }
        }
    } else {
        #pragma unroll
        for (int i = 0; i < 2; i++) {
            #pragma unroll
            for (int half = 0; half < 2; half++) {
                float mx = -1e30f;
                #pragma unroll
                for (int j = 0; j < 8; j++) {
                    mx = fmaxf(mx, acc[i][j][half*2+0]);
                    mx = fmaxf(mx, acc[i][j][half*2+1]);
                }
                float s = 0.f;
                #pragma unroll
                for (int j = 0; j < 8; j++) {
                    s += expf(acc[i][j][half*2+0] - mx);
                    s += expf(acc[i][j][half*2+1] - mx);
                }
                #pragma unroll
                for (int m = 1; m < 4; m <<= 1) {
                    float M2 = __shfl_xor_sync(0xffffffff, mx, m);
                    float S2 = __shfl_xor_sync(0xffffffff, s,  m);
                    float Mn = fmaxf(mx, M2);
                    s = s * expf(mx - Mn) + S2 * expf(M2 - Mn);
                    mx = Mn;
                }
                if (t == 0) {
                    int rloc = wm + i*16 + half*8 + g;
                    smx[wid & 1][rloc] = mx;
                    sms[wid & 1][rloc] = s;
                }
            }
        }
        __syncthreads();
        if (tid < 128) {
            int gm = bm + tid;
            if (gm < M) {
                float m0 = smx[0][tid], m1 = smx[1][tid];
                float Mn = fmaxf(m0, m1);
                float S  = sms[0][tid] * expf(m0 - Mn) + sms[1][tid] * expf(m1 - Mn);
                pmax[(size_t)blockIdx.x * 4096 + gm] = Mn;
                psum[(size_t)blockIdx.x * 4096 + gm] = S;
            }
        }
    }
}

// ---------------- 64-row MMA tile helper for fused kernels ----------------
// Computes acc[NJ][4] += A(64 x kLen) @ W(NJ*8 x kLen)^T for this block's warp.
// A fp32 (lda), W bf16 (ldw). kLen % 64 == 0.
template<int NJ>
__device__ __forceinline__ void mm_tile(const float* __restrict__ A, int lda,
                                        const __nv_bfloat16* __restrict__ W, int ldw,
                                        int wrow0, int k0, int kLen,
                                        __nv_bfloat16* As, __nv_bfloat16* Ws,
                                        float acc[NJ][4]) {
    const int tid  = threadIdx.x;
    const int lane = tid & 31;
    const int g    = lane >> 2;
    const int t    = lane & 3;

    for (int kt = k0; kt < k0 + kLen; kt += 64) {
        #pragma unroll
        for (int q = 0; q < 8; q++) {
            int f = q * 128 + tid;
            int row = f >> 4;
            int c4 = (f & 15) << 2;
            float4 v = *(const float4*)(A + (size_t)row * lda + kt + c4);
            *(uint32_t*)&As[row * SASTR + c4]     = packbf(v.x, v.y);
            *(uint32_t*)&As[row * SASTR + c4 + 2] = packbf(v.z, v.w);
        }
        #pragma unroll
        for (int q = 0; q < NJ/2; q++) {
            int f = q * 128 + tid;
            int row = f >> 3;
            int c8 = (f & 7) << 3;
            uint4 v = *(const uint4*)(W + (size_t)row * ldw + kt + c8);
            *(uint4*)&Ws[row * SASTR + c8] = v;
        }
        __syncthreads();
        #pragma unroll
        for (int kk = 0; kk < 4; kk++) {
            int ra0 = (wrow0 + g) * SASTR + kk*16;
            int ra1 = (wrow0 + 8 + g) * SASTR + kk*16;
            uint32_t a0 = *(const uint32_t*)&As[ra0 + 2*t];
            uint32_t a1 = *(const uint32_t*)&As[ra1 + 2*t];
            uint32_t a2 = *(const uint32_t*)&As[ra0 + 8 + 2*t];
            uint32_t a3 = *(const uint32_t*)&As[ra1 + 8 + 2*t];
            #pragma unroll
            for (int j = 0; j < NJ; j++) {
                int rb = (j*8 + g) * SASTR + kk*16;
                uint32_t b0 = *(const uint32_t*)&Ws[rb + 2*t];
                uint32_t b1 = *(const uint32_t*)&Ws[rb + 8 + 2*t];
                asm volatile(
                    "mma.sync.aligned.m16n8k16.row.col.f32.bf16.bf16.f32 "
                    "{%0,%1,%2,%3}, {%4,%5,%6,%7}, {%8,%9}, {%0,%1,%2,%3};"
                    : "+f"(acc[j][0]), "+f"(acc[j][1]),
                      "+f"(acc[j][2]), "+f"(acc[j][3])
                    : "r"(a0), "r"(a1), "r"(a2), "r"(a3),
                      "r"(b0), "r"(b1));
            }
        }
        __syncthreads();
    }
}

// ================= fused encoder (both directions) =================
// grid (256, 2), 128 threads. dir = blockIdx.y. 256 blocks per direction,
// block bx: n-tile (bx & 63), K-split s = bx >> 6 (Kper = 256).
__global__ __launch_bounds__(128, 4)
void enc_fused(const float* __restrict__ XF, const float* __restrict__ XB,
               float* __restrict__ OUTF, float* __restrict__ OUTB,
               float* __restrict__ HF, float* __restrict__ CF,
               float* __restrict__ HB_, float* __restrict__ CB_,
               float* __restrict__ PARTF, float* __restrict__ PARTB,
               const __nv_bfloat16* __restrict__ WF, const __nv_bfloat16* __restrict__ WB,
               const int* __restrict__ lens,
               float* __restrict__ HCAT, float* __restrict__ CCAT) {
    __shared__ __align__(16) __nv_bfloat16 As[64 * SASTR];
    __shared__ __align__(16) __nv_bfloat16 Ws[64 * SASTR];

    const int dir = blockIdx.y;
    const int bx  = blockIdx.x;
    const int tid = threadIdx.x;
    unsigned* cnt = &g_cnt[dir];

    const float* Xin = dir ? XB : XF;
    float* OUT = dir ? OUTB : OUTF;
    float* h   = dir ? HB_ : HF;
    float* c   = dir ? CB_ : CF;
    float* PART = dir ? PARTB : PARTF;
    const __nv_bfloat16* W = dir ? WB : WF;

    const int lane = tid & 31;
    const int wid  = tid >> 5;
    const int wm   = wid * 16;
    const int g    = lane >> 2;
    const int t    = lane & 3;
    const int bn   = (bx & 63) * 64;
    const int s    = bx >> 6;
    float* outsl = PART + (size_t)s * (BB*H4);

    // init h, c = 0
    {
        int i0 = bx * 256 + tid;
        h[i0] = 0.f; h[i0 + 128] = 0.f;
        c[i0] = 0.f; c[i0 + 128] = 0.f;
    }
    gbar(cnt, 256);

    for (int step = 0; step < TSRC; step++) {
        int tt = dir ? (TSRC - 1 - step) : step;
        // gemm: h(64x1024) @ W(4096x1024)^T slice
        float acc[8][4];
        #pragma unroll
        for (int j = 0; j < 8; j++)
            #pragma unroll
            for (int r = 0; r < 4; r++) acc[j][r] = 0.f;
        mm_tile<8>(h, HH, W + (size_t)bn * HH, HH, wm, s * 256, 256, As, Ws, acc);
        int r0 = wm + g, r1 = r0 + 8;
        #pragma unroll
        for (int j = 0; j < 8; j++) {
            int col = bn + j*8 + 2*t;
            *(float2*)(outsl + (size_t)r0 * H4 + col) = make_float2(acc[j][0], acc[j][1]);
            *(float2*)(outsl + (size_t)r1 * H4 + col) = make_float2(acc[j][2], acc[j][3]);
        }
        gbar(cnt, 256);

        // cell: 2 elems per thread
        const float* X = Xin + (size_t)tt * (BB*H4);
        #pragma unroll
        for (int e = 0; e < 2; e++) {
            int idx = bx * 256 + e * 128 + tid;
            int b = idx >> 10, j = idx & 1023;
            size_t base = (size_t)b * H4 + j;
            float gi = X[base], gf = X[base + HH], gg = X[base + 2*HH], go = X[base + 3*HH];
            #pragma unroll
            for (int q = 0; q < 4; q++) {
                const float* p = PART + (size_t)q * (BB*H4);
                gi += p[base]; gf += p[base + HH]; gg += p[base + 2*HH]; go += p[base + 3*HH];
            }
            float cold = c[idx];
            float c2 = sigm(gf) * cold + sigm(gi) * tanhf(gg);
            float h2 = sigm(go) * tanhf(c2);
            bool m = tt < lens[b];
            h[idx] = m ? h2 : h[idx];
            c[idx] = m ? c2 : cold;
            OUT[(size_t)tt * (BB*HH) + idx] = m ? h2 : 0.f;
        }
        gbar(cnt, 256);
    }

    // write final h/c into HCAT/CCAT halves
    #pragma unroll
    for (int e = 0; e < 2; e++) {
        int idx = bx * 256 + e * 128 + tid;
        int b = idx >> 10, j = idx & 1023;
        HCAT[(size_t)b * 2048 + dir * HH + j] = h[idx];
        CCAT[(size_t)b * 2048 + dir * HH + j] = c[idx];
    }
}

// ================= fused decoder =================
// grid 512, 128 threads.
__global__ __launch_bounds__(128, 4)
void dec_fused(const float* __restrict__ YW,
               float* __restrict__ H, float* __restrict__ C,
               float* __restrict__ ACAT, float* __restrict__ PART,
               const __nv_bfloat16* __restrict__ WCAT,
               const __nv_bfloat16* __restrict__ WCMB,
               const float* __restrict__ ENCP, const float* __restrict__ ENCH,
               const int* __restrict__ lens,
               float* __restrict__ ATT, float* __restrict__ OUTS) {
    __shared__ __align__(16) __nv_bfloat16 As[64 * SASTR];
    __shared__ __align__(16) __nv_bfloat16 Ws[64 * SASTR];
    __shared__ float e_s[64];
    __shared__ float alpha_s[64];

    const int bx  = blockIdx.x;
    const int tid = threadIdx.x;
    unsigned* cnt = &g_cnt[2];
    const int lane = tid & 31;
    const int wid  = tid >> 5;
    const int wm   = wid * 16;
    const int g    = lane >> 2;
    const int t    = lane & 3;

    // init ACAT: left = H (h0), right = 0
    #pragma unroll
    for (int e = 0; e < 2; e++) {
        int idx = bx * 256 + e * 128 + tid;   // 131072 total
        int b = idx >> 11, j = idx & 2047;
        ACAT[idx] = (j < 1024) ? H[b * HH + j] : 0.f;
    }
    gbar(cnt, 512);

    for (int step = 0; step < TD; step++) {
        // ---- gemm1: ACAT(64x2048) @ WCAT(4096x2048)^T, 64 n-tiles x 8 splits ----
        {
            const int bn = (bx & 63) * 64;
            const int s  = bx >> 6;      // 0..7
            float* outsl = PART + (size_t)s * (BB*H4);
            float acc[8][4];
            #pragma unroll
            for (int j = 0; j < 8; j++)
                #pragma unroll
                for (int r = 0; r < 4; r++) acc[j][r] = 0.f;
            mm_tile<8>(ACAT, 2*HH, WCAT + (size_t)bn * 2*HH, 2*HH, wm, s * 256, 256, As, Ws, acc);
            int r0 = wm + g, r1 = r0 + 8;
            #pragma unroll
            for (int j = 0; j < 8; j++) {
                int col = bn + j*8 + 2*t;
                *(float2*)(outsl + (size_t)r0 * H4 + col) = make_float2(acc[j][0], acc[j][1]);
                *(float2*)(outsl + (size_t)r1 * H4 + col) = make_float2(acc[j][2], acc[j][3]);
            }
        }
        gbar(cnt, 512);

        // ---- cell: 1 elem per thread ----
        {
            const float* X = YW + (size_t)step * (BB*H4);
            int idx = bx * 128 + tid;
            int b = idx >> 10, j = idx & 1023;
            size_t base = (size_t)b * H4 + j;
            float gi = X[base], gf = X[base + HH], gg = X[base + 2*HH], go = X[base + 3*HH];
            #pragma unroll
            for (int q = 0; q < 8; q++) {
                const float* p = PART + (size_t)q * (BB*H4);
                gi += p[base]; gf += p[base + HH]; gg += p[base + 2*HH]; go += p[base + 3*HH];
            }
            float cold = C[idx];
            float c2 = sigm(gf) * cold + sigm(gi) * tanhf(gg);
            float h2 = sigm(go) * tanhf(c2);
            H[idx] = h2;
            C[idx] = c2;
            ACAT[(size_t)b * 2048 + j] = h2;
        }
        gbar(cnt, 512);

        // ---- attention: blocks 0..63 (one per batch) ----
        if (bx < 64) {
            const int b = bx;
            const int len = lens[b];
            const float* hp = H + (size_t)b * HH;
            for (int tt = wid; tt < 64; tt += 4) {
                const float* ep = ENCP + ((size_t)b * 64 + tt) * HH;
                float sdot = 0.f;
                for (int k = lane; k < HH; k += 32) sdot += ep[k] * hp[k];
                #pragma unroll
                for (int m = 16; m > 0; m >>= 1) sdot += __shfl_xor_sync(0xffffffff, sdot, m);
                if (lane == 0) e_s[tt] = sdot;
            }
            __syncthreads();
            if (tid == 0) {
                float mx = -1e30f;
                for (int tt = 0; tt < len; tt++) mx = fmaxf(mx, e_s[tt]);
                float sm = 0.f;
                for (int tt = 0; tt < len; tt++) sm += expf(e_s[tt] - mx);
                float inv = 1.f / sm;
                for (int tt = 0; tt < 64; tt++)
                    alpha_s[tt] = (tt < len) ? expf(e_s[tt] - mx) * inv : 0.f;
            }
            __syncthreads();
            const float* eh = ENCH + (size_t)b * (64 * 2048);
            for (int d = tid; d < 2048; d += 128) {
                float sa = 0.f;
                for (int tt = 0; tt < len; tt++) sa += alpha_s[tt] * eh[(size_t)tt * 2048 + d];
                ATT[(size_t)b * 3072 + d] = sa;
            }
            for (int d = tid; d < 1024; d += 128)
                ATT[(size_t)b * 3072 + 2048 + d] = hp[d];
        }
        gbar(cnt, 512);

        // ---- gemm2 + tanh: ATT(64x3072) @ WCMB(1024x3072)^T, 32 blocks x 32-col tiles ----
        if (bx < 32) {
            const int bn = bx * 32;
            float acc[4][4];
            #pragma unroll
            for (int j = 0; j < 4; j++)
                #pragma unroll
                for (int r = 0; r < 4; r++) acc[j][r] = 0.f;
            mm_tile<4>(ATT, 3*HH, WCMB + (size_t)bn * 3*HH, 3*HH, wm, 0, 3*HH, As, Ws, acc);
            int r0 = wm + g, r1 = r0 + 8;
            float* O = OUTS + (size_t)step * (BB*HH);
            #pragma unroll
            for (int j = 0; j < 4; j++) {
                int col = bn + j*8 + 2*t;
                float v00 = tanhf(acc[j][0]), v01 = tanhf(acc[j][1]);
                float v10 = tanhf(acc[j][2]), v11 = tanhf(acc[j][3]);
                *(float2*)(O + (size_t)r0 * HH + col) = make_float2(v00, v01);
                *(float2*)(O + (size_t)r1 * HH + col) = make_float2(v10, v11);
                *(float2*)(ACAT + (size_t)r0 * 2048 + 1024 + col) = make_float2(v00, v01);
                *(float2*)(ACAT + (size_t)r1 * 2048 + 1024 + col) = make_float2(v10, v11);
            }
        }
        gbar(cnt, 512);
    }
}

// ---------------- fp32 small GEMM (one-off projections) ----------------
__global__ __launch_bounds__(256)
void pgemm(const float* __restrict__ A, int lda,
           const float* __restrict__ W, int ldw,
           float* __restrict__ out, int Ntot, int Kper, size_t slotStride) {
    __shared__ float As[16][68];
    __shared__ float Ws[16][68];
    const int bn = blockIdx.x * 64;
    const int s  = blockIdx.y;
    const int k0 = s * Kper;
    out += (size_t)s * slotStride;
    const int tid = threadIdx.x;
    const int lr = tid >> 2;
    const int lc = (tid & 3) << 2;
    const int ty = tid >> 4;
    const int tx = tid & 15;
    float acc[4][4];
    #pragma unroll
    for (int i = 0; i < 4; i++)
        #pragma unroll
        for (int j = 0; j < 4; j++) acc[i][j] = 0.f;

    for (int kt = k0; kt < k0 + Kper; kt += 16) {
        float4 v = *(const float4*)(A + (size_t)lr * lda + kt + lc);
        As[lc+0][lr] = v.x; As[lc+1][lr] = v.y; As[lc+2][lr] = v.z; As[lc+3][lr] = v.w;
        float4 w = *(const float4*)(W + (size_t)(bn + lr) * ldw + kt + lc);
        Ws[lc+0][lr] = w.x; Ws[lc+1][lr] = w.y; Ws[lc+2][lr] = w.z; Ws[lc+3][lr] = w.w;
        __syncthreads();
        #pragma unroll
        for (int k = 0; k < 16; k++) {
            float4 a = *(const float4*)&As[k][ty*4];
            float4 b = *(const float4*)&Ws[k][tx*4];
            float av[4] = {a.x,a.y,a.z,a.w};
            float bv[4] = {b.x,b.y,b.z,b.w};
            #pragma unroll
            for (int i = 0; i < 4; i++)
                #pragma unroll
                for (int j = 0; j < 4; j++) acc[i][j] += av[i] * bv[j];
        }
        __syncthreads();
    }
    #pragma unroll
    for (int i = 0; i < 4; i++) {
        int b = ty * 4 + i;
        #pragma unroll
        for (int j = 0; j < 4; j++)
            out[(size_t)b * Ntot + bn + tx * 4 + j] = acc[i][j];
    }
}

// ---------------- lse / gold / final ----------------
__global__ void lse_k(const float* __restrict__ pmax, const float* __restrict__ psum,
                      float* __restrict__ lse, int M) {
    int row = blockIdx.x * 4 + (threadIdx.x >> 5);
    int l = threadIdx.x & 31;
    if (row >= M) return;
    float Mx = -1e30f, S = 0.f;
    for (int c = l; c < 250; c += 32) {
        float m2 = pmax[(size_t)c * 4096 + row];
        float s2 = psum[(size_t)c * 4096 + row];
        float Mn = fmaxf(Mx, m2);
        S = S * expf(Mx - Mn) + s2 * expf(m2 - Mn);
        Mx = Mn;
    }
    #pragma unroll
    for (int m = 16; m > 0; m >>= 1) {
        float M2 = __shfl_xor_sync(0xffffffff, Mx, m);
        float S2 = __shfl_xor_sync(0xffffffff, S, m);
        float Mn = fmaxf(Mx, M2);
        S = S * expf(Mx - Mn) + S2 * expf(M2 - Mn);
        Mx = Mn;
    }
    if (l == 0) lse[row] = Mx + logf(S);
}

__global__ void gold_k(const float* __restrict__ outs, const __nv_bfloat16* __restrict__ Wv,
                       const int* __restrict__ tgt, float* __restrict__ gold, int M) {
    int row = blockIdx.x * 4 + (threadIdx.x >> 5);
    int l = threadIdx.x & 31;
    if (row >= M) return;
    int id = tgt[row + 64];
    const float* a = outs + (size_t)row * HH;
    const __nv_bfloat16* w = Wv + (size_t)id * HH;
    float s = 0.f;
    for (int k = l; k < HH; k += 32) {
        float av = __bfloat162float(__float2bfloat16(a[k]));
        s += av * __bfloat162float(w[k]);
    }
    #pragma unroll
    for (int m = 16; m > 0; m >>= 1) s += __shfl_xor_sync(0xffffffff, s, m);
    if (l == 0) gold[row] = s;
}

__global__ void final_k(const float* __restrict__ gold, const float* __restrict__ lse,
                        const int* __restrict__ tgt, float* __restrict__ out) {
    int b = threadIdx.x;
    if (b >= BB) return;
    float s = 0.f;
    for (int t = 0; t < TD; t++) {
        int r = t * BB + b;
        if (tgt[r + 64] != 0) s += gold[r] - lse[r];
    }
    out[b] = s;
}

// ---------------- host launch ----------------
extern "C" void kernel_launch(void* const* d_in, const int* in_sizes, int n_in,
                              void* d_out, int out_size) {
    const int*   src_pad = (const int*)  d_in[0];
    const int*   tgt_pad = (const int*)  d_in[1];
    const int*   lens    = (const int*)  d_in[2];
    const float* src_emb = (const float*)d_in[3];
    const float* dst_emb = (const float*)d_in[4];
    const float* Wihf = (const float*)d_in[5];
    const float* Whhf = (const float*)d_in[6];
    const float* bihf = (const float*)d_in[7];
    const float* bhhf = (const float*)d_in[8];
    const float* Wihb = (const float*)d_in[9];
    const float* Whhb = (const float*)d_in[10];
    const float* bihb = (const float*)d_in[11];
    const float* bhhb = (const float*)d_in[12];
    const float* Wihd = (const float*)d_in[13];
    const float* Whhd = (const float*)d_in[14];
    const float* bihd = (const float*)d_in[15];
    const float* bhhd = (const float*)d_in[16];
    const float* Whpr = (const float*)d_in[17];
    const float* Wcpr = (const float*)d_in[18];
    const float* Watt = (const float*)d_in[19];
    const float* Wcmb = (const float*)d_in[20];
    const float* Wvoc = (const float*)d_in[21];
    float* out = (float*)d_out;

    float* gb;
    cudaGetSymbolAddress((void**)&gb, g_buf);
    __nv_bfloat16* bb;
    cudaGetSymbolAddress((void**)&bb, g_bf);

    float* X    = gb + OFF_X;
    float* Y    = gb + OFF_Y;
    float* XF   = gb + OFF_XF;
    float* XB   = gb + OFF_XB;
    float* YW   = gb + OFF_YW;
    float* OUTF = gb + OFF_OUTF;
    float* OUTB = gb + OFF_OUTB;
    float* ENCH = gb + OFF_ENCH;
    float* ENCP = gb + OFF_ENCP;
    float* OUTS = gb + OFF_OUTS;
    float* HF   = gb + OFF_H;
    float* CF   = gb + OFF_C;
    float* H0   = gb + OFF_H0;
    float* C0   = gb + OFF_C0;
    float* HCAT = gb + OFF_HCAT;
    float* CCAT = gb + OFF_CCAT;
    float* ATT  = gb + OFF_ATT;
    float* ACAT = gb + OFF_ACAT;
    float* PART = gb + OFF_PART;
    float* BS   = gb + OFF_BS;
    float* GOLD = gb + OFF_GOLD;
    float* LSE  = gb + OFF_LSE;
    float* PMAX = gb + OFF_PMAX;
    float* PSUM = gb + OFF_PSUM;

    __nv_bfloat16* BWVOC = bb + BOFF_WVOC;
    __nv_bfloat16* BWHHF = bb + BOFF_WHHF;
    __nv_bfloat16* BWHHB = bb + BOFF_WHHB;
    __nv_bfloat16* BWCAT = bb + BOFF_WCAT;
    __nv_bfloat16* BWIHF = bb + BOFF_WIHF;
    __nv_bfloat16* BWIHB = bb + BOFF_WIHB;
    __nv_bfloat16* BWIHDY= bb + BOFF_WIHDY;
    __nv_bfloat16* BWATT = bb + BOFF_WATT;
    __nv_bfloat16* BWCMB = bb + BOFF_WCMB;

    const size_t SS1 = (size_t)BB * HH;

    auto g8 = [](size_t n) { return (unsigned)((n/8 + 255) / 256); };
    cvt_rows<<<g8((size_t)VV*HH), 256>>>(BWVOC, Wvoc, VV, HH, HH);
    cvt_rows<<<g8((size_t)H4*HH), 256>>>(BWHHF, Whhf, H4, HH, HH);
    cvt_rows<<<g8((size_t)H4*HH), 256>>>(BWHHB, Whhb, H4, HH, HH);
    cvt_rows<<<g8((size_t)H4*EE), 256>>>(BWIHF, Wihf, H4, EE, EE);
    cvt_rows<<<g8((size_t)H4*EE), 256>>>(BWIHB, Wihb, H4, EE, EE);
    cvt_rows<<<g8((size_t)H4*EE), 256>>>(BWIHDY, Wihd, H4, EE, 3*EE);
    cvt_rows<<<g8((size_t)HH*2*HH), 256>>>(BWATT, Watt, HH, 2*HH, 2*HH);
    cvt_rows<<<g8((size_t)HH*3*HH), 256>>>(BWCMB, Wcmb, HH, 3*HH, 3*HH);
    cvt_cat<<<g8((size_t)H4*2048), 256>>>(BWCAT, Whhd, Wihd);

    bias3_k<<<16, 256>>>(BS, bihf, bhhf, bihb, bhhb, bihd, bhhd);
    gather_k<<<TSRC*BB, 128>>>(X, src_emb, src_pad);
    gather_k<<<TD*BB, 128>>>(Y, dst_emb, tgt_pad);

    // input GEMMs (bf16 MMA)
    bgemm<false><<<dim3(32, 32), 256>>>(X, EE, BWIHF, EE, XF, H4, TSRC*BB, EE, BS, nullptr, nullptr);
    bgemm<false><<<dim3(32, 32), 256>>>(X, EE, BWIHB, EE, XB, H4, TSRC*BB, EE, BS + H4, nullptr, nullptr);
    bgemm<false><<<dim3(32, 32), 256>>>(Y, EE, BWIHDY, EE, YW, H4, TD*BB, EE, BS + 2*H4, nullptr, nullptr);

    // fused bi-directional encoder scan
    enc_fused<<<dim3(256, 2), 128>>>(XF, XB, OUTF, OUTB, HF, CF, H0, C0,
                                     PART, PART + 4 * (size_t)BB * H4,
                                     BWHHF, BWHHB, lens, HCAT, CCAT);

    ench_k<<<16384, 256>>>(ENCH, OUTF, OUTB);

    // h0 / c0 projections
    pgemm<<<dim3(16, 4), 256>>>(HCAT, 2*HH, Whpr, 2*HH, PART, HH, 512, SS1);
    sumsl_k<<<256, 256>>>(H0, PART, 4);
    pgemm<<<dim3(16, 4), 256>>>(CCAT, 2*HH, Wcpr, 2*HH, PART, HH, 512, SS1);
    sumsl_k<<<256, 256>>>(C0, PART, 4);

    // enc_proj
    bgemm<false><<<dim3(8, 32), 256>>>(ENCH, 2*HH, BWATT, 2*HH, ENCP, HH, TSRC*BB, 2*HH, nullptr, nullptr, nullptr);

    // fused decoder scan
    dec_fused<<<512, 128>>>(YW, H0, C0, ACAT, PART, BWCAT, BWCMB,
                            ENCP, ENCH, lens, ATT, OUTS);

    // vocab (bf16 MMA + fused chunk stats)
    bgemm<true><<<dim3(250, 32), 256>>>(OUTS, HH, BWVOC, HH, nullptr, 0, TD*BB, HH, nullptr, PMAX, PSUM);
    lse_k<<<1008, 128>>>(PMAX, PSUM, LSE, TD*BB);
    gold_k<<<1008, 128>>>(OUTS, BWVOC, tgt_pad, GOLD, TD*BB);
    final_k<<<1, 64>>>(GOLD, LSE, tgt_pad, out);
}

// round 7
// speedup vs baseline: 1.3506x; 1.3506x over previous
#include <cuda_runtime.h>
#include <cuda_bf16.h>
#include <math.h>
#include <stdint.h>

#define TSRC 64
#define BB   64
#define EE   512
#define HH   1024
#define H4   4096
#define VV   32000
#define TD   63

// ---------------- fp32 scratch ----------------
constexpr size_t SZ_X    = (size_t)TSRC*BB*EE;
constexpr size_t SZ_Y    = (size_t)TD*BB*EE;
constexpr size_t SZ_XF   = (size_t)TSRC*BB*H4;
constexpr size_t SZ_YW   = (size_t)TD*BB*H4;
constexpr size_t SZ_OUTH = (size_t)TSRC*BB*HH;
constexpr size_t SZ_ENCH = (size_t)BB*TSRC*2*HH;
constexpr size_t SZ_ENCP = (size_t)BB*TSRC*HH;
constexpr size_t SZ_OUTS = (size_t)TD*BB*HH;
constexpr size_t SZ_BH   = (size_t)BB*HH;
constexpr size_t SZ_CAT2 = (size_t)BB*2*HH;
constexpr size_t SZ_CAT3 = (size_t)BB*3*HH;
constexpr size_t SZ_ACAT = (size_t)BB*2*HH;
constexpr size_t SZ_PART = (size_t)12*BB*H4;
constexpr size_t SZ_BS   = (size_t)3*H4;
constexpr size_t SZ_ROWS = (size_t)4096;
constexpr size_t SZ_PM   = (size_t)250*4096;

constexpr size_t OFF_X    = 0;
constexpr size_t OFF_Y    = OFF_X    + SZ_X;
constexpr size_t OFF_XF   = OFF_Y    + SZ_Y;
constexpr size_t OFF_XB   = OFF_XF   + SZ_XF;
constexpr size_t OFF_YW   = OFF_XB   + SZ_XF;
constexpr size_t OFF_OUTF = OFF_YW   + SZ_YW;
constexpr size_t OFF_OUTB = OFF_OUTF + SZ_OUTH;
constexpr size_t OFF_ENCH = OFF_OUTB + SZ_OUTH;
constexpr size_t OFF_ENCP = OFF_ENCH + SZ_ENCH;
constexpr size_t OFF_OUTS = OFF_ENCP + SZ_ENCP;
constexpr size_t OFF_H    = OFF_OUTS + SZ_OUTS;
constexpr size_t OFF_C    = OFF_H    + SZ_BH;
constexpr size_t OFF_H0   = OFF_C    + SZ_BH;
constexpr size_t OFF_C0   = OFF_H0   + SZ_BH;
constexpr size_t OFF_HCAT = OFF_C0   + SZ_BH;
constexpr size_t OFF_CCAT = OFF_HCAT + SZ_CAT2;
constexpr size_t OFF_ATT  = OFF_CCAT + SZ_CAT2;
constexpr size_t OFF_ACAT = OFF_ATT  + SZ_CAT3;
constexpr size_t OFF_PART = OFF_ACAT + SZ_ACAT;
constexpr size_t OFF_BS   = OFF_PART + SZ_PART;
constexpr size_t OFF_GOLD = OFF_BS   + SZ_BS;
constexpr size_t OFF_LSE  = OFF_GOLD + SZ_ROWS;
constexpr size_t OFF_PMAX = OFF_LSE  + SZ_ROWS;
constexpr size_t OFF_PSUM = OFF_PMAX + SZ_PM;
constexpr size_t TOTAL    = OFF_PSUM + SZ_PM;

__device__ float g_buf[TOTAL];

// sense-reversing barrier state: arrivals on g_cnt (one line),
// waiters poll g_gen (a DIFFERENT line) with backoff.
__device__ unsigned g_cnt[4 * 32];            // id*32 -> 128B apart
__device__ volatile unsigned g_gen[4 * 32];

// ---------------- bf16 scratch ----------------
constexpr size_t BOFF_WVOC = 0;
constexpr size_t BOFF_WHHF = BOFF_WVOC + (size_t)VV*HH;
constexpr size_t BOFF_WHHB = BOFF_WHHF + (size_t)H4*HH;
constexpr size_t BOFF_WCAT = BOFF_WHHB + (size_t)H4*HH;
constexpr size_t BOFF_WIHF = BOFF_WCAT + (size_t)H4*2*HH;
constexpr size_t BOFF_WIHB = BOFF_WIHF + (size_t)H4*EE;
constexpr size_t BOFF_WIHDY= BOFF_WIHB + (size_t)H4*EE;
constexpr size_t BOFF_WATT = BOFF_WIHDY+ (size_t)H4*EE;
constexpr size_t BOFF_WCMB = BOFF_WATT + (size_t)HH*2*HH;
constexpr size_t BTOTAL    = BOFF_WCMB + (size_t)HH*3*HH;

__device__ __nv_bfloat16 g_bf[BTOTAL];

__device__ __forceinline__ float sigm(float x) { return 1.0f / (1.0f + expf(-x)); }

__device__ __forceinline__ uint32_t packbf(float lo, float hi) {
    uint32_t r;
    asm("cvt.rn.bf16x2.f32 %0, %1, %2;" : "=r"(r) : "f"(hi), "f"(lo));
    return r;
}

// grid-wide sense barrier over n blocks, slot id.
__device__ __forceinline__ void gbar(int id, unsigned n) {
    __syncthreads();
    if (threadIdx.x == 0) {
        unsigned gen = g_gen[id * 32];
        __threadfence();                       // make this block's writes visible
        unsigned prev = atomicAdd(&g_cnt[id * 32], 1u);
        if (prev == n - 1u) {
            atomicExch(&g_cnt[id * 32], 0u);   // reset before release
            __threadfence();
            g_gen[id * 32] = gen + 1u;         // release: wake waiters
        } else {
            int ns = 32;
            while (g_gen[id * 32] == gen) {
                __nanosleep(ns);
                if (ns < 2048) ns <<= 1;
            }
        }
        __threadfence();                       // acquire
    }
    __syncthreads();
}

// ---------------- utility kernels ----------------
__global__ void bias3_k(float* bs,
                        const float* __restrict__ a1, const float* __restrict__ a2,
                        const float* __restrict__ b1, const float* __restrict__ b2,
                        const float* __restrict__ c1, const float* __restrict__ c2) {
    int j = blockIdx.x * 256 + threadIdx.x;
    if (j < H4) {
        bs[j]        = a1[j] + a2[j];
        bs[H4 + j]   = b1[j] + b2[j];
        bs[2*H4 + j] = c1[j] + c2[j];
    }
}

__global__ void gather_k(float* __restrict__ out, const float* __restrict__ emb,
                         const int* __restrict__ idx) {
    int row = blockIdx.x;
    int id  = idx[row];
    const float4* s = (const float4*)(emb + (size_t)id * EE);
    float4* d = (float4*)(out + (size_t)row * EE);
    d[threadIdx.x] = s[threadIdx.x];
}

__global__ void cvt_rows(__nv_bfloat16* __restrict__ dst, const float* __restrict__ src,
                         int rows, int cols, int srcStride) {
    size_t n8 = (size_t)rows * cols / 8;
    size_t i = (size_t)blockIdx.x * 256 + threadIdx.x;
    if (i >= n8) return;
    size_t e = i * 8;
    int r = (int)(e / cols), c = (int)(e % cols);
    const float* p = src + (size_t)r * srcStride + c;
    float4 v0 = *(const float4*)p;
    float4 v1 = *(const float4*)(p + 4);
    uint4 o;
    o.x = packbf(v0.x, v0.y); o.y = packbf(v0.z, v0.w);
    o.z = packbf(v1.x, v1.y); o.w = packbf(v1.z, v1.w);
    *(uint4*)(dst + e) = o;
}

__global__ void cvt_cat(__nv_bfloat16* __restrict__ dst, const float* __restrict__ whh,
                        const float* __restrict__ wih) {
    size_t i = (size_t)blockIdx.x * 256 + threadIdx.x;
    if (i >= (size_t)H4 * 2048 / 8) return;
    size_t e = i * 8;
    int n = (int)(e >> 11), j = (int)(e & 2047);
    const float* p = (j < 1024) ? (whh + (size_t)n * HH + j)
                                : (wih + (size_t)n * 1536 + 512 + (j - 1024));
    float4 v0 = *(const float4*)p;
    float4 v1 = *(const float4*)(p + 4);
    uint4 o;
    o.x = packbf(v0.x, v0.y); o.y = packbf(v0.z, v0.w);
    o.z = packbf(v1.x, v1.y); o.w = packbf(v1.z, v1.w);
    *(uint4*)(dst + e) = o;
}

__global__ void ench_k(float* __restrict__ ench, const float* __restrict__ outf,
                       const float* __restrict__ outb) {
    int idx = blockIdx.x * 256 + threadIdx.x;
    int t = idx >> 16;
    int r = idx & 65535;
    int b = r >> 10, j = r & 1023;
    size_t dst = (size_t)b * (TSRC*2*HH) + (size_t)t * 2*HH + j;
    ench[dst]      = outf[idx];
    ench[dst + HH] = outb[idx];
}

__global__ void sumsl_k(float* __restrict__ dst, const float* __restrict__ part, int ns) {
    int idx = blockIdx.x * 256 + threadIdx.x;
    float s = 0.f;
    for (int q = 0; q < ns; q++) s += part[(size_t)q * 65536 + idx];
    dst[idx] = s;
}

// ================= bf16 tensor-core GEMM (big, parallel) =================
#define SASTR 72

template<bool FUSED>
__global__ __launch_bounds__(256)
void bgemm(const float* __restrict__ A, int lda,
           const __nv_bfloat16* __restrict__ B, int ldb,
           float* __restrict__ C, int ldc,
           int M, int K, const float* __restrict__ bias,
           float* __restrict__ pmax, float* __restrict__ psum) {
    __shared__ __align__(16) __nv_bfloat16 As[128 * SASTR];
    __shared__ __align__(16) __nv_bfloat16 Bs[128 * SASTR];
    __shared__ float smx[2][128];
    __shared__ float sms[2][128];

    const int bm = blockIdx.y * 128;
    const int bn = blockIdx.x * 128;
    const int tid  = threadIdx.x;
    const int lane = tid & 31;
    const int wid  = tid >> 5;
    const int wm   = (wid >> 1) * 32;
    const int wn   = (wid & 1) * 64;
    const int g    = lane >> 2;
    const int t    = lane & 3;

    float acc[2][8][4];
    #pragma unroll
    for (int i = 0; i < 2; i++)
        #pragma unroll
        for (int j = 0; j < 8; j++)
            #pragma unroll
            for (int r = 0; r < 4; r++) acc[i][j][r] = 0.f;

    for (int kt = 0; kt < K; kt += 64) {
        #pragma unroll
        for (int q = 0; q < 8; q++) {
            int f = q * 256 + tid;
            int row = f >> 4;
            int c4 = (f & 15) << 2;
            int gr = bm + row;
            float4 v = make_float4(0.f,0.f,0.f,0.f);
            if (gr < M) v = *(const float4*)(A + (size_t)gr * lda + kt + c4);
            *(uint32_t*)&As[row * SASTR + c4]     = packbf(v.x, v.y);
            *(uint32_t*)&As[row * SASTR + c4 + 2] = packbf(v.z, v.w);
        }
        #pragma unroll
        for (int q = 0; q < 4; q++) {
            int f = q * 256 + tid;
            int row = f >> 3;
            int c8 = (f & 7) << 3;
            uint4 v = *(const uint4*)(B + (size_t)(bn + row) * ldb + kt + c8);
            *(uint4*)&Bs[row * SASTR + c8] = v;
        }
        __syncthreads();

        #pragma unroll
        for (int kk = 0; kk < 4; kk++) {
            uint32_t bf[8][2];
            #pragma unroll
            for (int j = 0; j < 8; j++) {
                int rb = (wn + j*8 + g) * SASTR + kk*16;
                bf[j][0] = *(const uint32_t*)&Bs[rb + 2*t];
                bf[j][1] = *(const uint32_t*)&Bs[rb + 8 + 2*t];
            }
            #pragma unroll
            for (int i = 0; i < 2; i++) {
                int ra0 = (wm + i*16 + g) * SASTR + kk*16;
                int ra1 = (wm + i*16 + 8 + g) * SASTR + kk*16;
                uint32_t a0 = *(const uint32_t*)&As[ra0 + 2*t];
                uint32_t a1 = *(const uint32_t*)&As[ra1 + 2*t];
                uint32_t a2 = *(const uint32_t*)&As[ra0 + 8 + 2*t];
                uint32_t a3 = *(const uint32_t*)&As[ra1 + 8 + 2*t];
                #pragma unroll
                for (int j = 0; j < 8; j++) {
                    asm volatile(
                        "mma.sync.aligned.m16n8k16.row.col.f32.bf16.bf16.f32 "
                        "{%0,%1,%2,%3}, {%4,%5,%6,%7}, {%8,%9}, {%0,%1,%2,%3};"
                        : "+f"(acc[i][j][0]), "+f"(acc[i][j][1]),
                          "+f"(acc[i][j][2]), "+f"(acc[i][j][3])
                        : "r"(a0), "r"(a1), "r"(a2), "r"(a3),
                          "r"(bf[j][0]), "r"(bf[j][1]));
                }
            }
        }
        __syncthreads();
    }

    if (!FUSED) {
        #pragma unroll
        for (int i = 0; i < 2; i++) {
            int r0 = bm + wm + i*16 + g;
            int r1 = r0 + 8;
            #pragma unroll
            for (int j = 0; j < 8; j++) {
                int col = bn + wn + j*8 + 2*t;
                float b0 = bias ? bias[col]   : 0.f;
                float b1 = bias ? bias[col+1] : 0.f;
                if (r0 < M) *(float2*)(C + (size_t)r0 * ldc + col) =
                    make_float2(acc[i][j][0] + b0, acc[i][j][1] + b1);
                if (r1 < M) *(float2*)(C + (size_t)r1 * ldc + col) =
                    make_float2(acc[i][j][2] + b0, acc[i][j][3] + b1);
            }
        }
    } else {
        #pragma unroll
        for (int i = 0; i < 2; i++) {
            #pragma unroll
            for (int half = 0; half < 2; half++) {
                float mx = -1e30f;
                #pragma unroll
                for (int j = 0; j < 8; j++) {
                    mx = fmaxf(mx, acc[i][j][half*2+0]);
                    mx = fmaxf(mx, acc[i][j][half*2+1]);
                }
                float s = 0.f;
                #pragma unroll
                for (int j = 0; j < 8; j++) {
                    s += expf(acc[i][j][half*2+0] - mx);
                    s += expf(acc[i][j][half*2+1] - mx);
                }
                #pragma unroll
                for (int m = 1; m < 4; m <<= 1) {
                    float M2 = __shfl_xor_sync(0xffffffff, mx, m);
                    float S2 = __shfl_xor_sync(0xffffffff, s,  m);
                    float Mn = fmaxf(mx, M2);
                    s = s * expf(mx - Mn) + S2 * expf(M2 - Mn);
                    mx = Mn;
                }
                if (t == 0) {
                    int rloc = wm + i*16 + half*8 + g;
                    smx[wid & 1][rloc] = mx;
                    sms[wid & 1][rloc] = s;
                }
            }
        }
        __syncthreads();
        if (tid < 128) {
            int gm = bm + tid;
            if (gm < M) {
                float m0 = smx[0][tid], m1 = smx[1][tid];
                float Mn = fmaxf(m0, m1);
                float S  = sms[0][tid] * expf(m0 - Mn) + sms[1][tid] * expf(m1 - Mn);
                pmax[(size_t)blockIdx.x * 4096 + gm] = Mn;
                psum[(size_t)blockIdx.x * 4096 + gm] = S;
            }
        }
    }
}

// ---------------- 64-row MMA tile helper ----------------
template<int NJ>
__device__ __forceinline__ void mm_tile(const float* __restrict__ A, int lda,
                                        const __nv_bfloat16* __restrict__ W, int ldw,
                                        int wrow0, int k0, int kLen,
                                        __nv_bfloat16* As, __nv_bfloat16* Ws,
                                        float acc[NJ][4]) {
    const int tid  = threadIdx.x;
    const int lane = tid & 31;
    const int g    = lane >> 2;
    const int t    = lane & 3;

    for (int kt = k0; kt < k0 + kLen; kt += 64) {
        #pragma unroll
        for (int q = 0; q < 8; q++) {
            int f = q * 128 + tid;
            int row = f >> 4;
            int c4 = (f & 15) << 2;
            float4 v = *(const float4*)(A + (size_t)row * lda + kt + c4);
            *(uint32_t*)&As[row * SASTR + c4]     = packbf(v.x, v.y);
            *(uint32_t*)&As[row * SASTR + c4 + 2] = packbf(v.z, v.w);
        }
        #pragma unroll
        for (int q = 0; q < NJ/2; q++) {
            int f = q * 128 + tid;
            int row = f >> 3;
            int c8 = (f & 7) << 3;
            uint4 v = *(const uint4*)(W + (size_t)row * ldw + kt + c8);
            *(uint4*)&Ws[row * SASTR + c8] = v;
        }
        __syncthreads();
        #pragma unroll
        for (int kk = 0; kk < 4; kk++) {
            int ra0 = (wrow0 + g) * SASTR + kk*16;
            int ra1 = (wrow0 + 8 + g) * SASTR + kk*16;
            uint32_t a0 = *(const uint32_t*)&As[ra0 + 2*t];
            uint32_t a1 = *(const uint32_t*)&As[ra1 + 2*t];
            uint32_t a2 = *(const uint32_t*)&As[ra0 + 8 + 2*t];
            uint32_t a3 = *(const uint32_t*)&As[ra1 + 8 + 2*t];
            #pragma unroll
            for (int j = 0; j < NJ; j++) {
                int rb = (j*8 + g) * SASTR + kk*16;
                uint32_t b0 = *(const uint32_t*)&Ws[rb + 2*t];
                uint32_t b1 = *(const uint32_t*)&Ws[rb + 8 + 2*t];
                asm volatile(
                    "mma.sync.aligned.m16n8k16.row.col.f32.bf16.bf16.f32 "
                    "{%0,%1,%2,%3}, {%4,%5,%6,%7}, {%8,%9}, {%0,%1,%2,%3};"
                    : "+f"(acc[j][0]), "+f"(acc[j][1]),
                      "+f"(acc[j][2]), "+f"(acc[j][3])
                    : "r"(a0), "r"(a1), "r"(a2), "r"(a3),
                      "r"(b0), "r"(b1));
            }
        }
        __syncthreads();
    }
}

// ================= fused encoder (both directions) =================
__global__ __launch_bounds__(128, 4)
void enc_fused(const float* __restrict__ XF, const float* __restrict__ XB,
               float* __restrict__ OUTF, float* __restrict__ OUTB,
               float* __restrict__ HF, float* __restrict__ CF,
               float* __restrict__ HB_, float* __restrict__ CB_,
               float* __restrict__ PARTF, float* __restrict__ PARTB,
               const __nv_bfloat16* __restrict__ WF, const __nv_bfloat16* __restrict__ WB,
               const int* __restrict__ lens,
               float* __restrict__ HCAT, float* __restrict__ CCAT) {
    __shared__ __align__(16) __nv_bfloat16 As[64 * SASTR];
    __shared__ __align__(16) __nv_bfloat16 Ws[64 * SASTR];

    const int dir = blockIdx.y;
    const int bx  = blockIdx.x;
    const int tid = threadIdx.x;

    const float* Xin = dir ? XB : XF;
    float* OUT = dir ? OUTB : OUTF;
    float* h   = dir ? HB_ : HF;
    float* c   = dir ? CB_ : CF;
    float* PART = dir ? PARTB : PARTF;
    const __nv_bfloat16* W = dir ? WB : WF;

    const int lane = tid & 31;
    const int wid  = tid >> 5;
    const int wm   = wid * 16;
    const int g    = lane >> 2;
    const int t    = lane & 3;
    const int bn   = (bx & 63) * 64;
    const int s    = bx >> 6;
    float* outsl = PART + (size_t)s * (BB*H4);

    {
        int i0 = bx * 256 + tid;
        h[i0] = 0.f; h[i0 + 128] = 0.f;
        c[i0] = 0.f; c[i0 + 128] = 0.f;
    }
    gbar(dir, 256);

    for (int step = 0; step < TSRC; step++) {
        int tt = dir ? (TSRC - 1 - step) : step;
        float acc[8][4];
        #pragma unroll
        for (int j = 0; j < 8; j++)
            #pragma unroll
            for (int r = 0; r < 4; r++) acc[j][r] = 0.f;
        mm_tile<8>(h, HH, W + (size_t)bn * HH, HH, wm, s * 256, 256, As, Ws, acc);
        int r0 = wm + g, r1 = r0 + 8;
        #pragma unroll
        for (int j = 0; j < 8; j++) {
            int col = bn + j*8 + 2*t;
            *(float2*)(outsl + (size_t)r0 * H4 + col) = make_float2(acc[j][0], acc[j][1]);
            *(float2*)(outsl + (size_t)r1 * H4 + col) = make_float2(acc[j][2], acc[j][3]);
        }
        gbar(dir, 256);

        const float* X = Xin + (size_t)tt * (BB*H4);
        #pragma unroll
        for (int e = 0; e < 2; e++) {
            int idx = bx * 256 + e * 128 + tid;
            int b = idx >> 10, j = idx & 1023;
            size_t base = (size_t)b * H4 + j;
            float gi = X[base], gf = X[base + HH], gg = X[base + 2*HH], go = X[base + 3*HH];
            #pragma unroll
            for (int q = 0; q < 4; q++) {
                const float* p = PART + (size_t)q * (BB*H4);
                gi += p[base]; gf += p[base + HH]; gg += p[base + 2*HH]; go += p[base + 3*HH];
            }
            float cold = c[idx];
            float c2 = sigm(gf) * cold + sigm(gi) * tanhf(gg);
            float h2 = sigm(go) * tanhf(c2);
            bool m = tt < lens[b];
            h[idx] = m ? h2 : h[idx];
            c[idx] = m ? c2 : cold;
            OUT[(size_t)tt * (BB*HH) + idx] = m ? h2 : 0.f;
        }
        gbar(dir, 256);
    }

    #pragma unroll
    for (int e = 0; e < 2; e++) {
        int idx = bx * 256 + e * 128 + tid;
        int b = idx >> 10, j = idx & 1023;
        HCAT[(size_t)b * 2048 + dir * HH + j] = h[idx];
        CCAT[(size_t)b * 2048 + dir * HH + j] = c[idx];
    }
}

// ================= fused decoder =================
__global__ __launch_bounds__(128, 4)
void dec_fused(const float* __restrict__ YW,
               float* __restrict__ H, float* __restrict__ C,
               float* __restrict__ ACAT, float* __restrict__ PART,
               const __nv_bfloat16* __restrict__ WCAT,
               const __nv_bfloat16* __restrict__ WCMB,
               const float* __restrict__ ENCP, const float* __restrict__ ENCH,
               const int* __restrict__ lens,
               float* __restrict__ ATT, float* __restrict__ OUTS) {
    __shared__ __align__(16) __nv_bfloat16 As[64 * SASTR];
    __shared__ __align__(16) __nv_bfloat16 Ws[64 * SASTR];
    __shared__ float e_s[64];
    __shared__ float alpha_s[64];

    const int bx  = blockIdx.x;
    const int tid = threadIdx.x;
    const int lane = tid & 31;
    const int wid  = tid >> 5;
    const int wm   = wid * 16;
    const int g    = lane >> 2;
    const int t    = lane & 3;

    #pragma unroll
    for (int e = 0; e < 2; e++) {
        int idx = bx * 256 + e * 128 + tid;
        int b = idx >> 11, j = idx & 2047;
        ACAT[idx] = (j < 1024) ? H[b * HH + j] : 0.f;
    }
    gbar(2, 512);

    for (int step = 0; step < TD; step++) {
        {
            const int bn = (bx & 63) * 64;
            const int s  = bx >> 6;
            float* outsl = PART + (size_t)s * (BB*H4);
            float acc[8][4];
            #pragma unroll
            for (int j = 0; j < 8; j++)
                #pragma unroll
                for (int r = 0; r < 4; r++) acc[j][r] = 0.f;
            mm_tile<8>(ACAT, 2*HH, WCAT + (size_t)bn * 2*HH, 2*HH, wm, s * 256, 256, As, Ws, acc);
            int r0 = wm + g, r1 = r0 + 8;
            #pragma unroll
            for (int j = 0; j < 8; j++) {
                int col = bn + j*8 + 2*t;
                *(float2*)(outsl + (size_t)r0 * H4 + col) = make_float2(acc[j][0], acc[j][1]);
                *(float2*)(outsl + (size_t)r1 * H4 + col) = make_float2(acc[j][2], acc[j][3]);
            }
        }
        gbar(2, 512);

        {
            const float* X = YW + (size_t)step * (BB*H4);
            int idx = bx * 128 + tid;
            int b = idx >> 10, j = idx & 1023;
            size_t base = (size_t)b * H4 + j;
            float gi = X[base], gf = X[base + HH], gg = X[base + 2*HH], go = X[base + 3*HH];
            #pragma unroll
            for (int q = 0; q < 8; q++) {
                const float* p = PART + (size_t)q * (BB*H4);
                gi += p[base]; gf += p[base + HH]; gg += p[base + 2*HH]; go += p[base + 3*HH];
            }
            float cold = C[idx];
            float c2 = sigm(gf) * cold + sigm(gi) * tanhf(gg);
            float h2 = sigm(go) * tanhf(c2);
            H[idx] = h2;
            C[idx] = c2;
            ACAT[(size_t)b * 2048 + j] = h2;
        }
        gbar(2, 512);

        if (bx < 64) {
            const int b = bx;
            const int len = lens[b];
            const float* hp = H + (size_t)b * HH;
            for (int tt = wid; tt < 64; tt += 4) {
                const float* ep = ENCP + ((size_t)b * 64 + tt) * HH;
                float sdot = 0.f;
                for (int k = lane; k < HH; k += 32) sdot += ep[k] * hp[k];
                #pragma unroll
                for (int m = 16; m > 0; m >>= 1) sdot += __shfl_xor_sync(0xffffffff, sdot, m);
                if (lane == 0) e_s[tt] = sdot;
            }
            __syncthreads();
            if (tid == 0) {
                float mx = -1e30f;
                for (int tt = 0; tt < len; tt++) mx = fmaxf(mx, e_s[tt]);
                float sm = 0.f;
                for (int tt = 0; tt < len; tt++) sm += expf(e_s[tt] - mx);
                float inv = 1.f / sm;
                for (int tt = 0; tt < 64; tt++)
                    alpha_s[tt] = (tt < len) ? expf(e_s[tt] - mx) * inv : 0.f;
            }
            __syncthreads();
            const float* eh = ENCH + (size_t)b * (64 * 2048);
            for (int d = tid; d < 2048; d += 128) {
                float sa = 0.f;
                for (int tt = 0; tt < len; tt++) sa += alpha_s[tt] * eh[(size_t)tt * 2048 + d];
                ATT[(size_t)b * 3072 + d] = sa;
            }
            for (int d = tid; d < 1024; d += 128)
                ATT[(size_t)b * 3072 + 2048 + d] = hp[d];
        }
        gbar(2, 512);

        if (bx < 32) {
            const int bn = bx * 32;
            float acc[4][4];
            #pragma unroll
            for (int j = 0; j < 4; j++)
                #pragma unroll
                for (int r = 0; r < 4; r++) acc[j][r] = 0.f;
            mm_tile<4>(ATT, 3*HH, WCMB + (size_t)bn * 3*HH, 3*HH, wm, 0, 3*HH, As, Ws, acc);
            int r0 = wm + g, r1 = r0 + 8;
            float* O = OUTS + (size_t)step * (BB*HH);
            #pragma unroll
            for (int j = 0; j < 4; j++) {
                int col = bn + j*8 + 2*t;
                float v00 = tanhf(acc[j][0]), v01 = tanhf(acc[j][1]);
                float v10 = tanhf(acc[j][2]), v11 = tanhf(acc[j][3]);
                *(float2*)(O + (size_t)r0 * HH + col) = make_float2(v00, v01);
                *(float2*)(O + (size_t)r1 * HH + col) = make_float2(v10, v11);
                *(float2*)(ACAT + (size_t)r0 * 2048 + 1024 + col) = make_float2(v00, v01);
                *(float2*)(ACAT + (size_t)r1 * 2048 + 1024 + col) = make_float2(v10, v11);
            }
        }
        gbar(2, 512);
    }
}

// ---------------- fp32 small GEMM (one-off projections) ----------------
__global__ __launch_bounds__(256)
void pgemm(const float* __restrict__ A, int lda,
           const float* __restrict__ W, int ldw,
           float* __restrict__ out, int Ntot, int Kper, size_t slotStride) {
    __shared__ float As[16][68];
    __shared__ float Ws[16][68];
    const int bn = blockIdx.x * 64;
    const int s  = blockIdx.y;
    const int k0 = s * Kper;
    out += (size_t)s * slotStride;
    const int tid = threadIdx.x;
    const int lr = tid >> 2;
    const int lc = (tid & 3) << 2;
    const int ty = tid >> 4;
    const int tx = tid & 15;
    float acc[4][4];
    #pragma unroll
    for (int i = 0; i < 4; i++)
        #pragma unroll
        for (int j = 0; j < 4; j++) acc[i][j] = 0.f;

    for (int kt = k0; kt < k0 + Kper; kt += 16) {
        float4 v = *(const float4*)(A + (size_t)lr * lda + kt + lc);
        As[lc+0][lr] = v.x; As[lc+1][lr] = v.y; As[lc+2][lr] = v.z; As[lc+3][lr] = v.w;
        float4 w = *(const float4*)(W + (size_t)(bn + lr) * ldw + kt + lc);
        Ws[lc+0][lr] = w.x; Ws[lc+1][lr] = w.y; Ws[lc+2][lr] = w.z; Ws[lc+3][lr] = w.w;
        __syncthreads();
        #pragma unroll
        for (int k = 0; k < 16; k++) {
            float4 a = *(const float4*)&As[k][ty*4];
            float4 b = *(const float4*)&Ws[k][tx*4];
            float av[4] = {a.x,a.y,a.z,a.w};
            float bv[4] = {b.x,b.y,b.z,b.w};
            #pragma unroll
            for (int i = 0; i < 4; i++)
                #pragma unroll
                for (int j = 0; j < 4; j++) acc[i][j] += av[i] * bv[j];
        }
        __syncthreads();
    }
    #pragma unroll
    for (int i = 0; i < 4; i++) {
        int b = ty * 4 + i;
        #pragma unroll
        for (int j = 0; j < 4; j++)
            out[(size_t)b * Ntot + bn + tx * 4 + j] = acc[i][j];
    }
}

// ---------------- lse / gold / final ----------------
__global__ void lse_k(const float* __restrict__ pmax, const float* __restrict__ psum,
                      float* __restrict__ lse, int M) {
    int row = blockIdx.x * 4 + (threadIdx.x >> 5);
    int l = threadIdx.x & 31;
    if (row >= M) return;
    float Mx = -1e30f, S = 0.f;
    for (int c = l; c < 250; c += 32) {
        float m2 = pmax[(size_t)c * 4096 + row];
        float s2 = psum[(size_t)c * 4096 + row];
        float Mn = fmaxf(Mx, m2);
        S = S * expf(Mx - Mn) + s2 * expf(m2 - Mn);
        Mx = Mn;
    }
    #pragma unroll
    for (int m = 16; m > 0; m >>= 1) {
        float M2 = __shfl_xor_sync(0xffffffff, Mx, m);
        float S2 = __shfl_xor_sync(0xffffffff, S, m);
        float Mn = fmaxf(Mx, M2);
        S = S * expf(Mx - Mn) + S2 * expf(M2 - Mn);
        Mx = Mn;
    }
    if (l == 0) lse[row] = Mx + logf(S);
}

__global__ void gold_k(const float* __restrict__ outs, const __nv_bfloat16* __restrict__ Wv,
                       const int* __restrict__ tgt, float* __restrict__ gold, int M) {
    int row = blockIdx.x * 4 + (threadIdx.x >> 5);
    int l = threadIdx.x & 31;
    if (row >= M) return;
    int id = tgt[row + 64];
    const float* a = outs + (size_t)row * HH;
    const __nv_bfloat16* w = Wv + (size_t)id * HH;
    float s = 0.f;
    for (int k = l; k < HH; k += 32) {
        float av = __bfloat162float(__float2bfloat16(a[k]));
        s += av * __bfloat162float(w[k]);
    }
    #pragma unroll
    for (int m = 16; m > 0; m >>= 1) s += __shfl_xor_sync(0xffffffff, s, m);
    if (l == 0) gold[row] = s;
}

__global__ void final_k(const float* __restrict__ gold, const float* __restrict__ lse,
                        const int* __restrict__ tgt, float* __restrict__ out) {
    int b = threadIdx.x;
    if (b >= BB) return;
    float s = 0.f;
    for (int t = 0; t < TD; t++) {
        int r = t * BB + b;
        if (tgt[r + 64] != 0) s += gold[r] - lse[r];
    }
    out[b] = s;
}

// ---------------- host launch ----------------
extern "C" void kernel_launch(void* const* d_in, const int* in_sizes, int n_in,
                              void* d_out, int out_size) {
    const int*   src_pad = (const int*)  d_in[0];
    const int*   tgt_pad = (const int*)  d_in[1];
    const int*   lens    = (const int*)  d_in[2];
    const float* src_emb = (const float*)d_in[3];
    const float* dst_emb = (const float*)d_in[4];
    const float* Wihf = (const float*)d_in[5];
    const float* Whhf = (const float*)d_in[6];
    const float* bihf = (const float*)d_in[7];
    const float* bhhf = (const float*)d_in[8];
    const float* Wihb = (const float*)d_in[9];
    const float* Whhb = (const float*)d_in[10];
    const float* bihb = (const float*)d_in[11];
    const float* bhhb = (const float*)d_in[12];
    const float* Wihd = (const float*)d_in[13];
    const float* Whhd = (const float*)d_in[14];
    const float* bihd = (const float*)d_in[15];
    const float* bhhd = (const float*)d_in[16];
    const float* Whpr = (const float*)d_in[17];
    const float* Wcpr = (const float*)d_in[18];
    const float* Watt = (const float*)d_in[19];
    const float* Wcmb = (const float*)d_in[20];
    const float* Wvoc = (const float*)d_in[21];
    float* out = (float*)d_out;

    float* gb;
    cudaGetSymbolAddress((void**)&gb, g_buf);
    __nv_bfloat16* bb;
    cudaGetSymbolAddress((void**)&bb, g_bf);

    float* X    = gb + OFF_X;
    float* Y    = gb + OFF_Y;
    float* XF   = gb + OFF_XF;
    float* XB   = gb + OFF_XB;
    float* YW   = gb + OFF_YW;
    float* OUTF = gb + OFF_OUTF;
    float* OUTB = gb + OFF_OUTB;
    float* ENCH = gb + OFF_ENCH;
    float* ENCP = gb + OFF_ENCP;
    float* OUTS = gb + OFF_OUTS;
    float* HF   = gb + OFF_H;
    float* CF   = gb + OFF_C;
    float* H0   = gb + OFF_H0;
    float* C0   = gb + OFF_C0;
    float* HCAT = gb + OFF_HCAT;
    float* CCAT = gb + OFF_CCAT;
    float* ATT  = gb + OFF_ATT;
    float* ACAT = gb + OFF_ACAT;
    float* PART = gb + OFF_PART;
    float* BS   = gb + OFF_BS;
    float* GOLD = gb + OFF_GOLD;
    float* LSE  = gb + OFF_LSE;
    float* PMAX = gb + OFF_PMAX;
    float* PSUM = gb + OFF_PSUM;

    __nv_bfloat16* BWVOC = bb + BOFF_WVOC;
    __nv_bfloat16* BWHHF = bb + BOFF_WHHF;
    __nv_bfloat16* BWHHB = bb + BOFF_WHHB;
    __nv_bfloat16* BWCAT = bb + BOFF_WCAT;
    __nv_bfloat16* BWIHF = bb + BOFF_WIHF;
    __nv_bfloat16* BWIHB = bb + BOFF_WIHB;
    __nv_bfloat16* BWIHDY= bb + BOFF_WIHDY;
    __nv_bfloat16* BWATT = bb + BOFF_WATT;
    __nv_bfloat16* BWCMB = bb + BOFF_WCMB;

    const size_t SS1 = (size_t)BB * HH;

    auto g8 = [](size_t n) { return (unsigned)((n/8 + 255) / 256); };
    cvt_rows<<<g8((size_t)VV*HH), 256>>>(BWVOC, Wvoc, VV, HH, HH);
    cvt_rows<<<g8((size_t)H4*HH), 256>>>(BWHHF, Whhf, H4, HH, HH);
    cvt_rows<<<g8((size_t)H4*HH), 256>>>(BWHHB, Whhb, H4, HH, HH);
    cvt_rows<<<g8((size_t)H4*EE), 256>>>(BWIHF, Wihf, H4, EE, EE);
    cvt_rows<<<g8((size_t)H4*EE), 256>>>(BWIHB, Wihb, H4, EE, EE);
    cvt_rows<<<g8((size_t)H4*EE), 256>>>(BWIHDY, Wihd, H4, EE, 3*EE);
    cvt_rows<<<g8((size_t)HH*2*HH), 256>>>(BWATT, Watt, HH, 2*HH, 2*HH);
    cvt_rows<<<g8((size_t)HH*3*HH), 256>>>(BWCMB, Wcmb, HH, 3*HH, 3*HH);
    cvt_cat<<<g8((size_t)H4*2048), 256>>>(BWCAT, Whhd, Wihd);

    bias3_k<<<16, 256>>>(BS, bihf, bhhf, bihb, bhhb, bihd, bhhd);
    gather_k<<<TSRC*BB, 128>>>(X, src_emb, src_pad);
    gather_k<<<TD*BB, 128>>>(Y, dst_emb, tgt_pad);

    bgemm<false><<<dim3(32, 32), 256>>>(X, EE, BWIHF, EE, XF, H4, TSRC*BB, EE, BS, nullptr, nullptr);
    bgemm<false><<<dim3(32, 32), 256>>>(X, EE, BWIHB, EE, XB, H4, TSRC*BB, EE, BS + H4, nullptr, nullptr);
    bgemm<false><<<dim3(32, 32), 256>>>(Y, EE, BWIHDY, EE, YW, H4, TD*BB, EE, BS + 2*H4, nullptr, nullptr);

    enc_fused<<<dim3(256, 2), 128>>>(XF, XB, OUTF, OUTB, HF, CF, H0, C0,
                                     PART, PART + 4 * (size_t)BB * H4,
                                     BWHHF, BWHHB, lens, HCAT, CCAT);

    ench_k<<<16384, 256>>>(ENCH, OUTF, OUTB);

    pgemm<<<dim3(16, 4), 256>>>(HCAT, 2*HH, Whpr, 2*HH, PART, HH, 512, SS1);
    sumsl_k<<<256, 256>>>(H0, PART, 4);
    pgemm<<<dim3(16, 4), 256>>>(CCAT, 2*HH, Wcpr, 2*HH, PART, HH, 512, SS1);
    sumsl_k<<<256, 256>>>(C0, PART, 4);

    bgemm<false><<<dim3(8, 32), 256>>>(ENCH, 2*HH, BWATT, 2*HH, ENCP, HH, TSRC*BB, 2*HH, nullptr, nullptr, nullptr);

    dec_fused<<<512, 128>>>(YW, H0, C0, ACAT, PART, BWCAT, BWCMB,
                            ENCP, ENCH, lens, ATT, OUTS);

    bgemm<true><<<dim3(250, 32), 256>>>(OUTS, HH, BWVOC, HH, nullptr, 0, TD*BB, HH, nullptr, PMAX, PSUM);
    lse_k<<<1008, 128>>>(PMAX, PSUM, LSE, TD*BB);
    gold_k<<<1008, 128>>>(OUTS, BWVOC, tgt_pad, GOLD, TD*BB);
    final_k<<<1, 64>>>(GOLD, LSE, tgt_pad, out);
}

// round 8
// speedup vs baseline: 2.6704x; 1.9772x over previous
#include <cuda_runtime.h>
#include <cuda_bf16.h>
#include <math.h>
#include <stdint.h>

#define TSRC 64
#define BB   64
#define EE   512
#define HH   1024
#define H4   4096
#define VV   32000
#define TD   63

// ---------------- fp32 scratch ----------------
constexpr size_t SZ_X    = (size_t)TSRC*BB*EE;
constexpr size_t SZ_Y    = (size_t)TD*BB*EE;
constexpr size_t SZ_XF   = (size_t)TSRC*BB*H4;
constexpr size_t SZ_YW   = (size_t)TD*BB*H4;
constexpr size_t SZ_OUTH = (size_t)TSRC*BB*HH;
constexpr size_t SZ_ENCH = (size_t)BB*TSRC*2*HH;
constexpr size_t SZ_ENCP = (size_t)BB*TSRC*HH;
constexpr size_t SZ_OUTS = (size_t)TD*BB*HH;
constexpr size_t SZ_BH   = (size_t)BB*HH;
constexpr size_t SZ_CAT2 = (size_t)BB*2*HH;
constexpr size_t SZ_CAT3 = (size_t)BB*3*HH;
constexpr size_t SZ_ACAT = (size_t)BB*2*HH;
constexpr size_t SZ_PART = (size_t)12*BB*H4;
constexpr size_t SZ_BS   = (size_t)3*H4;
constexpr size_t SZ_ROWS = (size_t)4096;
constexpr size_t SZ_PM   = (size_t)250*4096;
constexpr size_t SZ_EW   = (size_t)4096*1024;

constexpr size_t OFF_X    = 0;
constexpr size_t OFF_Y    = OFF_X    + SZ_X;
constexpr size_t OFF_XF   = OFF_Y    + SZ_Y;
constexpr size_t OFF_XB   = OFF_XF   + SZ_XF;
constexpr size_t OFF_YW   = OFF_XB   + SZ_XF;
constexpr size_t OFF_OUTF = OFF_YW   + SZ_YW;
constexpr size_t OFF_OUTB = OFF_OUTF + SZ_OUTH;
constexpr size_t OFF_ENCH = OFF_OUTB + SZ_OUTH;
constexpr size_t OFF_ENCP = OFF_ENCH + SZ_ENCH;
constexpr size_t OFF_OUTS = OFF_ENCP + SZ_ENCP;
constexpr size_t OFF_H    = OFF_OUTS + SZ_OUTS;
constexpr size_t OFF_C    = OFF_H    + SZ_BH;
constexpr size_t OFF_H0   = OFF_C    + SZ_BH;
constexpr size_t OFF_C0   = OFF_H0   + SZ_BH;
constexpr size_t OFF_HCAT = OFF_C0   + SZ_BH;
constexpr size_t OFF_CCAT = OFF_HCAT + SZ_CAT2;
constexpr size_t OFF_ATT  = OFF_CCAT + SZ_CAT2;   // reused: ALPHA lives here
constexpr size_t OFF_ACAT = OFF_ATT  + SZ_CAT3;
constexpr size_t OFF_PART = OFF_ACAT + SZ_ACAT;
constexpr size_t OFF_BS   = OFF_PART + SZ_PART;
constexpr size_t OFF_GOLD = OFF_BS   + SZ_BS;
constexpr size_t OFF_LSE  = OFF_GOLD + SZ_ROWS;
constexpr size_t OFF_PMAX = OFF_LSE  + SZ_ROWS;
constexpr size_t OFF_PSUM = OFF_PMAX + SZ_PM;
constexpr size_t OFF_EW   = OFF_PSUM + SZ_PM;
constexpr size_t OFF_EWT  = OFF_EW   + SZ_EW;
constexpr size_t TOTAL    = OFF_EWT  + SZ_EW;

__device__ float g_buf[TOTAL];
__device__ unsigned g_cnt[4 * 32];
__device__ volatile unsigned g_gen[4 * 32];

// ---------------- bf16 scratch ----------------
constexpr size_t BOFF_WVOC = 0;
constexpr size_t BOFF_WHHF = BOFF_WVOC + (size_t)VV*HH;
constexpr size_t BOFF_WHHB = BOFF_WHHF + (size_t)H4*HH;
constexpr size_t BOFF_WCAT = BOFF_WHHB + (size_t)H4*HH;
constexpr size_t BOFF_WIHF = BOFF_WCAT + (size_t)H4*2*HH;
constexpr size_t BOFF_WIHB = BOFF_WIHF + (size_t)H4*EE;
constexpr size_t BOFF_WIHDY= BOFF_WIHB + (size_t)H4*EE;
constexpr size_t BOFF_WATT = BOFF_WIHDY+ (size_t)H4*EE;
constexpr size_t BOFF_WCMB = BOFF_WATT + (size_t)HH*2*HH;
constexpr size_t BTOTAL    = BOFF_WCMB + (size_t)HH*3*HH;

__device__ __nv_bfloat16 g_bf[BTOTAL];

__device__ __forceinline__ float sigm(float x) { return 1.0f / (1.0f + expf(-x)); }

__device__ __forceinline__ uint32_t packbf(float lo, float hi) {
    uint32_t r;
    asm("cvt.rn.bf16x2.f32 %0, %1, %2;" : "=r"(r) : "f"(hi), "f"(lo));
    return r;
}

__device__ __forceinline__ void gbar(int id, unsigned n) {
    __syncthreads();
    if (threadIdx.x == 0) {
        unsigned gen = g_gen[id * 32];
        __threadfence();
        unsigned prev = atomicAdd(&g_cnt[id * 32], 1u);
        if (prev == n - 1u) {
            atomicExch(&g_cnt[id * 32], 0u);
            __threadfence();
            g_gen[id * 32] = gen + 1u;
        } else {
            int ns = 32;
            while (g_gen[id * 32] == gen) {
                __nanosleep(ns);
                if (ns < 2048) ns <<= 1;
            }
        }
        __threadfence();
    }
    __syncthreads();
}

// ---------------- merged conversion kernel (launch #1) ----------------
__global__ void cvt_all(const float* __restrict__ Wvoc,
                        const float* __restrict__ Whhf, const float* __restrict__ Whhb,
                        const float* __restrict__ Whhd, const float* __restrict__ Wihd,
                        const float* __restrict__ Wihf, const float* __restrict__ Wihb,
                        const float* __restrict__ Watt, const float* __restrict__ Wcmb) {
    constexpr size_t E0 = (size_t)VV*HH;
    constexpr size_t E1 = E0 + (size_t)H4*HH;
    constexpr size_t E2 = E1 + (size_t)H4*HH;
    constexpr size_t E3 = E2 + (size_t)H4*2*HH;
    constexpr size_t E4 = E3 + (size_t)H4*EE;
    constexpr size_t E5 = E4 + (size_t)H4*EE;
    constexpr size_t E6 = E5 + (size_t)H4*EE;
    constexpr size_t E7 = E6 + (size_t)HH*2*HH;
    constexpr size_t E8 = E7 + (size_t)HH*3*HH;
    size_t e = ((size_t)blockIdx.x * 256 + threadIdx.x) * 8;
    if (e >= E8) return;
    const float* p;
    if (e < E0) {
        p = Wvoc + e;                                     // cols=HH, dense
    } else if (e < E1) {
        p = Whhf + (e - E0);
    } else if (e < E2) {
        p = Whhb + (e - E1);
    } else if (e < E3) {
        size_t l = e - E2;
        int n = (int)(l >> 11), j = (int)(l & 2047);
        p = (j < 1024) ? (Whhd + (size_t)n * HH + j)
                       : (Wihd + (size_t)n * 1536 + 512 + (j - 1024));
    } else if (e < E4) {
        p = Wihf + (e - E3);
    } else if (e < E5) {
        p = Wihb + (e - E4);
    } else if (e < E6) {
        size_t l = e - E5;
        int n = (int)(l >> 9), j = (int)(l & 511);
        p = Wihd + (size_t)n * 1536 + j;                  // cols 512 of 1536
    } else if (e < E7) {
        p = Watt + (e - E6);
    } else {
        p = Wcmb + (e - E7);
    }
    float4 v0 = *(const float4*)p;
    float4 v1 = *(const float4*)(p + 4);
    uint4 o;
    o.x = packbf(v0.x, v0.y); o.y = packbf(v0.z, v0.w);
    o.z = packbf(v1.x, v1.y); o.w = packbf(v1.z, v1.w);
    *(uint4*)(g_bf + e) = o;
}

// ---------------- merged gather + bias kernel (launch #2) ----------------
__global__ void gath_bias(float* __restrict__ X, float* __restrict__ Y,
                          const float* __restrict__ semb, const float* __restrict__ demb,
                          const int* __restrict__ sidx, const int* __restrict__ didx,
                          float* __restrict__ bs,
                          const float* __restrict__ a1, const float* __restrict__ a2,
                          const float* __restrict__ b1, const float* __restrict__ b2,
                          const float* __restrict__ c1, const float* __restrict__ c2) {
    int bx = blockIdx.x;
    if (bx < TSRC*BB) {
        int id = sidx[bx];
        ((float4*)(X + (size_t)bx * EE))[threadIdx.x] =
            ((const float4*)(semb + (size_t)id * EE))[threadIdx.x];
    } else if (bx < TSRC*BB + TD*BB) {
        int row = bx - TSRC*BB;
        int id = didx[row];
        ((float4*)(Y + (size_t)row * EE))[threadIdx.x] =
            ((const float4*)(demb + (size_t)id * EE))[threadIdx.x];
    } else {
        int j = (bx - (TSRC*BB + TD*BB)) * 128 + threadIdx.x;
        if (j < H4) {
            bs[j]        = a1[j] + a2[j];
            bs[H4 + j]   = b1[j] + b2[j];
            bs[2*H4 + j] = c1[j] + c2[j];
        }
    }
}

__global__ void ench_k(float* __restrict__ ench, const float* __restrict__ outf,
                       const float* __restrict__ outb) {
    int idx = blockIdx.x * 256 + threadIdx.x;
    int t = idx >> 16;
    int r = idx & 65535;
    int b = r >> 10, j = r & 1023;
    size_t dst = (size_t)b * (TSRC*2*HH) + (size_t)t * 2*HH + j;
    ench[dst]      = outf[idx];
    ench[dst + HH] = outb[idx];
}

__global__ void sumsl_k(float* __restrict__ dst, const float* __restrict__ part, int ns) {
    int idx = blockIdx.x * 256 + threadIdx.x;
    float s = 0.f;
    for (int q = 0; q < ns; q++) s += part[(size_t)q * 65536 + idx];
    dst[idx] = s;
}

// transpose EW[(b*64+t)][n] -> EWT[b][n][t]
__global__ void ewt_k(float* __restrict__ ewt, const float* __restrict__ ew) {
    __shared__ float tile[32][33];
    int b = blockIdx.z, nt = blockIdx.x * 32, tt = blockIdx.y * 32;
    int tx = threadIdx.x & 31, ty0 = threadIdx.x >> 5;
    #pragma unroll
    for (int r = ty0; r < 32; r += 8)
        tile[r][tx] = ew[((size_t)(b*64 + tt + r)) * 1024 + nt + tx];
    __syncthreads();
    #pragma unroll
    for (int r = ty0; r < 32; r += 8)
        ewt[((size_t)b * 1024 + nt + r) * 64 + tt + tx] = tile[tx][r];
}

// ================= bf16 tensor-core GEMM (big, parallel) =================
#define SASTR 72

template<bool FUSED>
__global__ __launch_bounds__(256)
void bgemm(const float* __restrict__ A, int lda,
           const __nv_bfloat16* __restrict__ B, int ldb,
           float* __restrict__ C, int ldc,
           int M, int K, const float* __restrict__ bias,
           float* __restrict__ pmax, float* __restrict__ psum) {
    __shared__ __align__(16) __nv_bfloat16 As[128 * SASTR];
    __shared__ __align__(16) __nv_bfloat16 Bs[128 * SASTR];
    __shared__ float smx[2][128];
    __shared__ float sms[2][128];

    const int bm = blockIdx.y * 128;
    const int bn = blockIdx.x * 128;
    const int tid  = threadIdx.x;
    const int lane = tid & 31;
    const int wid  = tid >> 5;
    const int wm   = (wid >> 1) * 32;
    const int wn   = (wid & 1) * 64;
    const int g    = lane >> 2;
    const int t    = lane & 3;

    float acc[2][8][4];
    #pragma unroll
    for (int i = 0; i < 2; i++)
        #pragma unroll
        for (int j = 0; j < 8; j++)
            #pragma unroll
            for (int r = 0; r < 4; r++) acc[i][j][r] = 0.f;

    for (int kt = 0; kt < K; kt += 64) {
        #pragma unroll
        for (int q = 0; q < 8; q++) {
            int f = q * 256 + tid;
            int row = f >> 4;
            int c4 = (f & 15) << 2;
            int gr = bm + row;
            float4 v = make_float4(0.f,0.f,0.f,0.f);
            if (gr < M) v = *(const float4*)(A + (size_t)gr * lda + kt + c4);
            *(uint32_t*)&As[row * SASTR + c4]     = packbf(v.x, v.y);
            *(uint32_t*)&As[row * SASTR + c4 + 2] = packbf(v.z, v.w);
        }
        #pragma unroll
        for (int q = 0; q < 4; q++) {
            int f = q * 256 + tid;
            int row = f >> 3;
            int c8 = (f & 7) << 3;
            uint4 v = *(const uint4*)(B + (size_t)(bn + row) * ldb + kt + c8);
            *(uint4*)&Bs[row * SASTR + c8] = v;
        }
        __syncthreads();

        #pragma unroll
        for (int kk = 0; kk < 4; kk++) {
            uint32_t bf[8][2];
            #pragma unroll
            for (int j = 0; j < 8; j++) {
                int rb = (wn + j*8 + g) * SASTR + kk*16;
                bf[j][0] = *(const uint32_t*)&Bs[rb + 2*t];
                bf[j][1] = *(const uint32_t*)&Bs[rb + 8 + 2*t];
            }
            #pragma unroll
            for (int i = 0; i < 2; i++) {
                int ra0 = (wm + i*16 + g) * SASTR + kk*16;
                int ra1 = (wm + i*16 + 8 + g) * SASTR + kk*16;
                uint32_t a0 = *(const uint32_t*)&As[ra0 + 2*t];
                uint32_t a1 = *(const uint32_t*)&As[ra1 + 2*t];
                uint32_t a2 = *(const uint32_t*)&As[ra0 + 8 + 2*t];
                uint32_t a3 = *(const uint32_t*)&As[ra1 + 8 + 2*t];
                #pragma unroll
                for (int j = 0; j < 8; j++) {
                    asm volatile(
                        "mma.sync.aligned.m16n8k16.row.col.f32.bf16.bf16.f32 "
                        "{%0,%1,%2,%3}, {%4,%5,%6,%7}, {%8,%9}, {%0,%1,%2,%3};"
                        : "+f"(acc[i][j][0]), "+f"(acc[i][j][1]),
                          "+f"(acc[i][j][2]), "+f"(acc[i][j][3])
                        : "r"(a0), "r"(a1), "r"(a2), "r"(a3),
                          "r"(bf[j][0]), "r"(bf[j][1]));
                }
            }
        }
        __syncthreads();
    }

    if (!FUSED) {
        #pragma unroll
        for (int i = 0; i < 2; i++) {
            int r0 = bm + wm + i*16 + g;
            int r1 = r0 + 8;
            #pragma unroll
            for (int j = 0; j < 8; j++) {
                int col = bn + wn + j*8 + 2*t;
                float b0 = bias ? bias[col]   : 0.f;
                float b1 = bias ? bias[col+1] : 0.f;
                if (r0 < M) *(float2*)(C + (size_t)r0 * ldc + col) =
                    make_float2(acc[i][j][0] + b0, acc[i][j][1] + b1);
                if (r1 < M) *(float2*)(C + (size_t)r1 * ldc + col) =
                    make_float2(acc[i][j][2] + b0, acc[i][j][3] + b1);
            }
        }
    } else {
        #pragma unroll
        for (int i = 0; i < 2; i++) {
            #pragma unroll
            for (int half = 0; half < 2; half++) {
                float mx = -1e30f;
                #pragma unroll
                for (int j = 0; j < 8; j++) {
                    mx = fmaxf(mx, acc[i][j][half*2+0]);
                    mx = fmaxf(mx, acc[i][j][half*2+1]);
                }
                float s = 0.f;
                #pragma unroll
                for (int j = 0; j < 8; j++) {
                    s += expf(acc[i][j][half*2+0] - mx);
                    s += expf(acc[i][j][half*2+1] - mx);
                }
                #pragma unroll
                for (int m = 1; m < 4; m <<= 1) {
                    float M2 = __shfl_xor_sync(0xffffffff, mx, m);
                    float S2 = __shfl_xor_sync(0xffffffff, s,  m);
                    float Mn = fmaxf(mx, M2);
                    s = s * expf(mx - Mn) + S2 * expf(M2 - Mn);
                    mx = Mn;
                }
                if (t == 0) {
                    int rloc = wm + i*16 + half*8 + g;
                    smx[wid & 1][rloc] = mx;
                    sms[wid & 1][rloc] = s;
                }
            }
        }
        __syncthreads();
        if (tid < 128) {
            int gm = bm + tid;
            if (gm < M) {
                float m0 = smx[0][tid], m1 = smx[1][tid];
                float Mn = fmaxf(m0, m1);
                float S  = sms[0][tid] * expf(m0 - Mn) + sms[1][tid] * expf(m1 - Mn);
                pmax[(size_t)blockIdx.x * 4096 + gm] = Mn;
                psum[(size_t)blockIdx.x * 4096 + gm] = S;
            }
        }
    }
}

// ---------------- 64-row MMA tile helper ----------------
template<int NJ>
__device__ __forceinline__ void mm_tile(const float* __restrict__ A, int lda,
                                        const __nv_bfloat16* __restrict__ W, int ldw,
                                        int wrow0, int k0, int kLen,
                                        __nv_bfloat16* As, __nv_bfloat16* Ws,
                                        float acc[NJ][4]) {
    const int tid  = threadIdx.x;
    const int lane = tid & 31;
    const int g    = lane >> 2;
    const int t    = lane & 3;

    for (int kt = k0; kt < k0 + kLen; kt += 64) {
        #pragma unroll
        for (int q = 0; q < 8; q++) {
            int f = q * 128 + tid;
            int row = f >> 4;
            int c4 = (f & 15) << 2;
            float4 v = *(const float4*)(A + (size_t)row * lda + kt + c4);
            *(uint32_t*)&As[row * SASTR + c4]     = packbf(v.x, v.y);
            *(uint32_t*)&As[row * SASTR + c4 + 2] = packbf(v.z, v.w);
        }
        #pragma unroll
        for (int q = 0; q < NJ/2; q++) {
            int f = q * 128 + tid;
            int row = f >> 3;
            int c8 = (f & 7) << 3;
            uint4 v = *(const uint4*)(W + (size_t)row * ldw + kt + c8);
            *(uint4*)&Ws[row * SASTR + c8] = v;
        }
        __syncthreads();
        #pragma unroll
        for (int kk = 0; kk < 4; kk++) {
            int ra0 = (wrow0 + g) * SASTR + kk*16;
            int ra1 = (wrow0 + 8 + g) * SASTR + kk*16;
            uint32_t a0 = *(const uint32_t*)&As[ra0 + 2*t];
            uint32_t a1 = *(const uint32_t*)&As[ra1 + 2*t];
            uint32_t a2 = *(const uint32_t*)&As[ra0 + 8 + 2*t];
            uint32_t a3 = *(const uint32_t*)&As[ra1 + 8 + 2*t];
            #pragma unroll
            for (int j = 0; j < NJ; j++) {
                int rb = (j*8 + g) * SASTR + kk*16;
                uint32_t b0 = *(const uint32_t*)&Ws[rb + 2*t];
                uint32_t b1 = *(const uint32_t*)&Ws[rb + 8 + 2*t];
                asm volatile(
                    "mma.sync.aligned.m16n8k16.row.col.f32.bf16.bf16.f32 "
                    "{%0,%1,%2,%3}, {%4,%5,%6,%7}, {%8,%9}, {%0,%1,%2,%3};"
                    : "+f"(acc[j][0]), "+f"(acc[j][1]),
                      "+f"(acc[j][2]), "+f"(acc[j][3])
                    : "r"(a0), "r"(a1), "r"(a2), "r"(a3),
                      "r"(b0), "r"(b1));
            }
        }
        __syncthreads();
    }
}

// ================= fused encoder (both directions) =================
__global__ __launch_bounds__(128, 4)
void enc_fused(const float* __restrict__ XF, const float* __restrict__ XB,
               float* __restrict__ OUTF, float* __restrict__ OUTB,
               float* __restrict__ HF, float* __restrict__ CF,
               float* __restrict__ HB_, float* __restrict__ CB_,
               float* __restrict__ PARTF, float* __restrict__ PARTB,
               const __nv_bfloat16* __restrict__ WF, const __nv_bfloat16* __restrict__ WB,
               const int* __restrict__ lens,
               float* __restrict__ HCAT, float* __restrict__ CCAT) {
    __shared__ __align__(16) __nv_bfloat16 As[64 * SASTR];
    __shared__ __align__(16) __nv_bfloat16 Ws[64 * SASTR];

    const int dir = blockIdx.y;
    const int bx  = blockIdx.x;
    const int tid = threadIdx.x;

    const float* Xin = dir ? XB : XF;
    float* OUT = dir ? OUTB : OUTF;
    float* h   = dir ? HB_ : HF;
    float* c   = dir ? CB_ : CF;
    float* PART = dir ? PARTB : PARTF;
    const __nv_bfloat16* W = dir ? WB : WF;

    const int lane = tid & 31;
    const int wid  = tid >> 5;
    const int wm   = wid * 16;
    const int g    = lane >> 2;
    const int t    = lane & 3;
    const int bn   = (bx & 63) * 64;
    const int s    = bx >> 6;
    float* outsl = PART + (size_t)s * (BB*H4);

    {
        int i0 = bx * 256 + tid;
        h[i0] = 0.f; h[i0 + 128] = 0.f;
        c[i0] = 0.f; c[i0 + 128] = 0.f;
    }
    gbar(dir, 256);

    for (int step = 0; step < TSRC; step++) {
        int tt = dir ? (TSRC - 1 - step) : step;
        float acc[8][4];
        #pragma unroll
        for (int j = 0; j < 8; j++)
            #pragma unroll
            for (int r = 0; r < 4; r++) acc[j][r] = 0.f;
        mm_tile<8>(h, HH, W + (size_t)bn * HH, HH, wm, s * 256, 256, As, Ws, acc);
        int r0 = wm + g, r1 = r0 + 8;
        #pragma unroll
        for (int j = 0; j < 8; j++) {
            int col = bn + j*8 + 2*t;
            *(float2*)(outsl + (size_t)r0 * H4 + col) = make_float2(acc[j][0], acc[j][1]);
            *(float2*)(outsl + (size_t)r1 * H4 + col) = make_float2(acc[j][2], acc[j][3]);
        }
        gbar(dir, 256);

        const float* X = Xin + (size_t)tt * (BB*H4);
        #pragma unroll
        for (int e = 0; e < 2; e++) {
            int idx = bx * 256 + e * 128 + tid;
            int b = idx >> 10, j = idx & 1023;
            size_t base = (size_t)b * H4 + j;
            float gi = X[base], gf = X[base + HH], gg = X[base + 2*HH], go = X[base + 3*HH];
            #pragma unroll
            for (int q = 0; q < 4; q++) {
                const float* p = PART + (size_t)q * (BB*H4);
                gi += p[base]; gf += p[base + HH]; gg += p[base + 2*HH]; go += p[base + 3*HH];
            }
            float cold = c[idx];
            float c2 = sigm(gf) * cold + sigm(gi) * tanhf(gg);
            float h2 = sigm(go) * tanhf(c2);
            bool m = tt < lens[b];
            h[idx] = m ? h2 : h[idx];
            c[idx] = m ? c2 : cold;
            OUT[(size_t)tt * (BB*HH) + idx] = m ? h2 : 0.f;
        }
        gbar(dir, 256);
    }

    #pragma unroll
    for (int e = 0; e < 2; e++) {
        int idx = bx * 256 + e * 128 + tid;
        int b = idx >> 10, j = idx & 1023;
        HCAT[(size_t)b * 2048 + dir * HH + j] = h[idx];
        CCAT[(size_t)b * 2048 + dir * HH + j] = c[idx];
    }
}

// ================= fused decoder (EW-restructured) =================
__global__ __launch_bounds__(128, 4)
void dec_fused(const float* __restrict__ YW,
               float* __restrict__ H, float* __restrict__ C,
               float* __restrict__ ACAT, float* __restrict__ PART,
               const __nv_bfloat16* __restrict__ WCAT,
               const __nv_bfloat16* __restrict__ WCH,   // Wcmb cols 2048..3071, ldw 3072
               const float* __restrict__ ENCP,
               const float* __restrict__ EWT,           // [b][n][t]
               float* __restrict__ ALPHA,               // [b][t]
               const int* __restrict__ lens,
               float* __restrict__ OUTS) {
    __shared__ __align__(16) __nv_bfloat16 As[64 * SASTR];
    __shared__ __align__(16) __nv_bfloat16 Ws[64 * SASTR];
    __shared__ float e_s[64];
    __shared__ float alpha_s[64];

    const int bx  = blockIdx.x;
    const int tid = threadIdx.x;
    const int lane = tid & 31;
    const int wid  = tid >> 5;
    const int wm   = wid * 16;
    const int g    = lane >> 2;
    const int t    = lane & 3;

    float* HPART = PART + 8 * (size_t)BB * H4;   // 4 slices of BB*HH

    #pragma unroll
    for (int e = 0; e < 2; e++) {
        int idx = bx * 256 + e * 128 + tid;
        int b = idx >> 11, j = idx & 2047;
        ACAT[idx] = (j < 1024) ? H[b * HH + j] : 0.f;
    }
    gbar(2, 512);

    for (int step = 0; step < TD; step++) {
        // ---- R1: gemm1  ACAT(64x2048) @ WCAT^T ----
        {
            const int bn = (bx & 63) * 64;
            const int s  = bx >> 6;
            float* outsl = PART + (size_t)s * (BB*H4);
            float acc[8][4];
            #pragma unroll
            for (int j = 0; j < 8; j++)
                #pragma unroll
                for (int r = 0; r < 4; r++) acc[j][r] = 0.f;
            mm_tile<8>(ACAT, 2*HH, WCAT + (size_t)bn * 2*HH, 2*HH, wm, s * 256, 256, As, Ws, acc);
            int r0 = wm + g, r1 = r0 + 8;
            #pragma unroll
            for (int j = 0; j < 8; j++) {
                int col = bn + j*8 + 2*t;
                *(float2*)(outsl + (size_t)r0 * H4 + col) = make_float2(acc[j][0], acc[j][1]);
                *(float2*)(outsl + (size_t)r1 * H4 + col) = make_float2(acc[j][2], acc[j][3]);
            }
        }
        gbar(2, 512);

        // ---- R2: cell ----
        {
            const float* X = YW + (size_t)step * (BB*H4);
            int idx = bx * 128 + tid;
            int b = idx >> 10, j = idx & 1023;
            size_t base = (size_t)b * H4 + j;
            float gi = X[base], gf = X[base + HH], gg = X[base + 2*HH], go = X[base + 3*HH];
            #pragma unroll
            for (int q = 0; q < 8; q++) {
                const float* p = PART + (size_t)q * (BB*H4);
                gi += p[base]; gf += p[base + HH]; gg += p[base + 2*HH]; go += p[base + 3*HH];
            }
            float cold = C[idx];
            float c2 = sigm(gf) * cold + sigm(gi) * tanhf(gg);
            float h2 = sigm(go) * tanhf(c2);
            H[idx] = h2;
            C[idx] = c2;
            ACAT[(size_t)b * 2048 + j] = h2;
        }
        gbar(2, 512);

        // ---- R3: scores+softmax (blocks 0..63)  ||  HPART = h2 @ WCH^T (blocks 448..511) ----
        if (bx < 64) {
            const int b = bx;
            const int len = lens[b];
            const float* hp = H + (size_t)b * HH;
            for (int tt = wid; tt < 64; tt += 4) {
                const float* ep = ENCP + ((size_t)b * 64 + tt) * HH;
                float sdot = 0.f;
                for (int k = lane; k < HH; k += 32) sdot += ep[k] * hp[k];
                #pragma unroll
                for (int m = 16; m > 0; m >>= 1) sdot += __shfl_xor_sync(0xffffffff, sdot, m);
                if (lane == 0) e_s[tt] = sdot;
            }
            __syncthreads();
            if (tid == 0) {
                float mx = -1e30f;
                for (int tt = 0; tt < len; tt++) mx = fmaxf(mx, e_s[tt]);
                float sm = 0.f;
                for (int tt = 0; tt < len; tt++) sm += expf(e_s[tt] - mx);
                float inv = 1.f / sm;
                for (int tt = 0; tt < 64; tt++)
                    alpha_s[tt] = (tt < len) ? expf(e_s[tt] - mx) * inv : 0.f;
            }
            __syncthreads();
            if (tid < 64) ALPHA[b * 64 + tid] = alpha_s[tid];
        } else if (bx >= 448) {
            const int blk = bx - 448;
            const int tile = blk & 15;           // 16 col-tiles of 64
            const int spl  = blk >> 4;           // 4 K-splits of 256
            float* outsl = HPART + (size_t)spl * (BB*HH);
            float acc[8][4];
            #pragma unroll
            for (int j = 0; j < 8; j++)
                #pragma unroll
                for (int r = 0; r < 4; r++) acc[j][r] = 0.f;
            mm_tile<8>(H, HH, WCH + (size_t)(tile * 64) * 3072, 3072, wm, spl * 256, 256, As, Ws, acc);
            int r0 = wm + g, r1 = r0 + 8;
            #pragma unroll
            for (int j = 0; j < 8; j++) {
                int col = tile * 64 + j*8 + 2*t;
                *(float2*)(outsl + (size_t)r0 * HH + col) = make_float2(acc[j][0], acc[j][1]);
                *(float2*)(outsl + (size_t)r1 * HH + col) = make_float2(acc[j][2], acc[j][3]);
            }
        }
        gbar(2, 512);

        // ---- R4: O = tanh(alpha @ EWT + sum HPART) ----
        {
            int idx = bx * 128 + tid;            // 65536
            int b = idx >> 10, n = idx & 1023;
            const float4* al = (const float4*)(ALPHA + b * 64);
            const float4* ev = (const float4*)(EWT + ((size_t)b * 1024 + n) * 64);
            float s = 0.f;
            #pragma unroll
            for (int q4 = 0; q4 < 16; q4++) {
                float4 a4 = al[q4];
                float4 e4 = ev[q4];
                s += a4.x * e4.x + a4.y * e4.y + a4.z * e4.z + a4.w * e4.w;
            }
            #pragma unroll
            for (int q = 0; q < 4; q++) s += HPART[(size_t)q * (BB*HH) + idx];
            float v = tanhf(s);
            OUTS[(size_t)step * (BB*HH) + idx] = v;
            ACAT[(size_t)b * 2048 + 1024 + n] = v;
        }
        gbar(2, 512);
    }
}

// ---------------- fp32 small GEMM (one-off projections) ----------------
__global__ __launch_bounds__(256)
void pgemm(const float* __restrict__ A, int lda,
           const float* __restrict__ W, int ldw,
           float* __restrict__ out, int Ntot, int Kper, size_t slotStride) {
    __shared__ float As[16][68];
    __shared__ float Ws[16][68];
    const int bn = blockIdx.x * 64;
    const int s  = blockIdx.y;
    const int k0 = s * Kper;
    out += (size_t)s * slotStride;
    const int tid = threadIdx.x;
    const int lr = tid >> 2;
    const int lc = (tid & 3) << 2;
    const int ty = tid >> 4;
    const int tx = tid & 15;
    float acc[4][4];
    #pragma unroll
    for (int i = 0; i < 4; i++)
        #pragma unroll
        for (int j = 0; j < 4; j++) acc[i][j] = 0.f;

    for (int kt = k0; kt < k0 + Kper; kt += 16) {
        float4 v = *(const float4*)(A + (size_t)lr * lda + kt + lc);
        As[lc+0][lr] = v.x; As[lc+1][lr] = v.y; As[lc+2][lr] = v.z; As[lc+3][lr] = v.w;
        float4 w = *(const float4*)(W + (size_t)(bn + lr) * ldw + kt + lc);
        Ws[lc+0][lr] = w.x; Ws[lc+1][lr] = w.y; Ws[lc+2][lr] = w.z; Ws[lc+3][lr] = w.w;
        __syncthreads();
        #pragma unroll
        for (int k = 0; k < 16; k++) {
            float4 a = *(const float4*)&As[k][ty*4];
            float4 b = *(const float4*)&Ws[k][tx*4];
            float av[4] = {a.x,a.y,a.z,a.w};
            float bv[4] = {b.x,b.y,b.z,b.w};
            #pragma unroll
            for (int i = 0; i < 4; i++)
                #pragma unroll
                for (int j = 0; j < 4; j++) acc[i][j] += av[i] * bv[j];
        }
        __syncthreads();
    }
    #pragma unroll
    for (int i = 0; i < 4; i++) {
        int b = ty * 4 + i;
        #pragma unroll
        for (int j = 0; j < 4; j++)
            out[(size_t)b * Ntot + bn + tx * 4 + j] = acc[i][j];
    }
}

// ---------------- lse / gold / final ----------------
__global__ void lse_k(const float* __restrict__ pmax, const float* __restrict__ psum,
                      float* __restrict__ lse, int M) {
    int row = blockIdx.x * 4 + (threadIdx.x >> 5);
    int l = threadIdx.x & 31;
    if (row >= M) return;
    float Mx = -1e30f, S = 0.f;
    for (int c = l; c < 250; c += 32) {
        float m2 = pmax[(size_t)c * 4096 + row];
        float s2 = psum[(size_t)c * 4096 + row];
        float Mn = fmaxf(Mx, m2);
        S = S * expf(Mx - Mn) + s2 * expf(m2 - Mn);
        Mx = Mn;
    }
    #pragma unroll
    for (int m = 16; m > 0; m >>= 1) {
        float M2 = __shfl_xor_sync(0xffffffff, Mx, m);
        float S2 = __shfl_xor_sync(0xffffffff, S, m);
        float Mn = fmaxf(Mx, M2);
        S = S * expf(Mx - Mn) + S2 * expf(M2 - Mn);
        Mx = Mn;
    }
    if (l == 0) lse[row] = Mx + logf(S);
}

__global__ void gold_k(const float* __restrict__ outs, const __nv_bfloat16* __restrict__ Wv,
                       const int* __restrict__ tgt, float* __restrict__ gold, int M) {
    int row = blockIdx.x * 4 + (threadIdx.x >> 5);
    int l = threadIdx.x & 31;
    if (row >= M) return;
    int id = tgt[row + 64];
    const float* a = outs + (size_t)row * HH;
    const __nv_bfloat16* w = Wv + (size_t)id * HH;
    float s = 0.f;
    for (int k = l; k < HH; k += 32) {
        float av = __bfloat162float(__float2bfloat16(a[k]));
        s += av * __bfloat162float(w[k]);
    }
    #pragma unroll
    for (int m = 16; m > 0; m >>= 1) s += __shfl_xor_sync(0xffffffff, s, m);
    if (l == 0) gold[row] = s;
}

__global__ void final_k(const float* __restrict__ gold, const float* __restrict__ lse,
                        const int* __restrict__ tgt, float* __restrict__ out) {
    int b = threadIdx.x;
    if (b >= BB) return;
    float s = 0.f;
    for (int t = 0; t < TD; t++) {
        int r = t * BB + b;
        if (tgt[r + 64] != 0) s += gold[r] - lse[r];
    }
    out[b] = s;
}

// ---------------- host launch ----------------
extern "C" void kernel_launch(void* const* d_in, const int* in_sizes, int n_in,
                              void* d_out, int out_size) {
    const int*   src_pad = (const int*)  d_in[0];
    const int*   tgt_pad = (const int*)  d_in[1];
    const int*   lens    = (const int*)  d_in[2];
    const float* src_emb = (const float*)d_in[3];
    const float* dst_emb = (const float*)d_in[4];
    const float* Wihf = (const float*)d_in[5];
    const float* Whhf = (const float*)d_in[6];
    const float* bihf = (const float*)d_in[7];
    const float* bhhf = (const float*)d_in[8];
    const float* Wihb = (const float*)d_in[9];
    const float* Whhb = (const float*)d_in[10];
    const float* bihb = (const float*)d_in[11];
    const float* bhhb = (const float*)d_in[12];
    const float* Wihd = (const float*)d_in[13];
    const float* Whhd = (const float*)d_in[14];
    const float* bihd = (const float*)d_in[15];
    const float* bhhd = (const float*)d_in[16];
    const float* Whpr = (const float*)d_in[17];
    const float* Wcpr = (const float*)d_in[18];
    const float* Watt = (const float*)d_in[19];
    const float* Wcmb = (const float*)d_in[20];
    const float* Wvoc = (const float*)d_in[21];
    float* out = (float*)d_out;

    float* gb;
    cudaGetSymbolAddress((void**)&gb, g_buf);
    __nv_bfloat16* bb;
    cudaGetSymbolAddress((void**)&bb, g_bf);

    float* X    = gb + OFF_X;
    float* Y    = gb + OFF_Y;
    float* XF   = gb + OFF_XF;
    float* XB   = gb + OFF_XB;
    float* YW   = gb + OFF_YW;
    float* OUTF = gb + OFF_OUTF;
    float* OUTB = gb + OFF_OUTB;
    float* ENCH = gb + OFF_ENCH;
    float* ENCP = gb + OFF_ENCP;
    float* OUTS = gb + OFF_OUTS;
    float* HF   = gb + OFF_H;
    float* CF   = gb + OFF_C;
    float* H0   = gb + OFF_H0;
    float* C0   = gb + OFF_C0;
    float* HCAT = gb + OFF_HCAT;
    float* CCAT = gb + OFF_CCAT;
    float* ALPHA= gb + OFF_ATT;
    float* ACAT = gb + OFF_ACAT;
    float* PART = gb + OFF_PART;
    float* BS   = gb + OFF_BS;
    float* GOLD = gb + OFF_GOLD;
    float* LSE  = gb + OFF_LSE;
    float* PMAX = gb + OFF_PMAX;
    float* PSUM = gb + OFF_PSUM;
    float* EW   = gb + OFF_EW;
    float* EWT  = gb + OFF_EWT;

    __nv_bfloat16* BWVOC = bb + BOFF_WVOC;
    __nv_bfloat16* BWHHF = bb + BOFF_WHHF;
    __nv_bfloat16* BWHHB = bb + BOFF_WHHB;
    __nv_bfloat16* BWCAT = bb + BOFF_WCAT;
    __nv_bfloat16* BWIHF = bb + BOFF_WIHF;
    __nv_bfloat16* BWIHB = bb + BOFF_WIHB;
    __nv_bfloat16* BWIHDY= bb + BOFF_WIHDY;
    __nv_bfloat16* BWATT = bb + BOFF_WATT;
    __nv_bfloat16* BWCMB = bb + BOFF_WCMB;

    const size_t SS1 = (size_t)BB * HH;

    // 1: all weight conversions
    constexpr size_t NCVT = ((size_t)VV*HH + 2*(size_t)H4*HH + (size_t)H4*2*HH
                           + 3*(size_t)H4*EE + (size_t)HH*2*HH + (size_t)HH*3*HH) / 8;
    cvt_all<<<(unsigned)((NCVT + 255) / 256), 256>>>(Wvoc, Whhf, Whhb, Whhd, Wihd,
                                                     Wihf, Wihb, Watt, Wcmb);
    // 2: embeddings gather + bias sums
    gath_bias<<<TSRC*BB + TD*BB + 32, 128>>>(X, Y, src_emb, dst_emb, src_pad, tgt_pad,
                                             BS, bihf, bhhf, bihb, bhhb, bihd, bhhd);
    // 3-5: input GEMMs
    bgemm<false><<<dim3(32, 32), 256>>>(X, EE, BWIHF, EE, XF, H4, TSRC*BB, EE, BS, nullptr, nullptr);
    bgemm<false><<<dim3(32, 32), 256>>>(X, EE, BWIHB, EE, XB, H4, TSRC*BB, EE, BS + H4, nullptr, nullptr);
    bgemm<false><<<dim3(32, 32), 256>>>(Y, EE, BWIHDY, EE, YW, H4, TD*BB, EE, BS + 2*H4, nullptr, nullptr);

    // 6: fused bi-directional encoder scan (ncu -s 5 -c 1 captures this)
    enc_fused<<<dim3(256, 2), 128>>>(XF, XB, OUTF, OUTB, HF, CF, H0, C0,
                                     PART, PART + 4 * (size_t)BB * H4,
                                     BWHHF, BWHHB, lens, HCAT, CCAT);

    ench_k<<<16384, 256>>>(ENCH, OUTF, OUTB);

    pgemm<<<dim3(16, 4), 256>>>(HCAT, 2*HH, Whpr, 2*HH, PART, HH, 512, SS1);
    sumsl_k<<<256, 256>>>(H0, PART, 4);
    pgemm<<<dim3(16, 4), 256>>>(CCAT, 2*HH, Wcpr, 2*HH, PART, HH, 512, SS1);
    sumsl_k<<<256, 256>>>(C0, PART, 4);

    // enc_proj and EW = ENCH @ Wcmb[:, :2048]^T
    bgemm<false><<<dim3(8, 32), 256>>>(ENCH, 2*HH, BWATT, 2*HH, ENCP, HH, TSRC*BB, 2*HH, nullptr, nullptr, nullptr);
    bgemm<false><<<dim3(8, 32), 256>>>(ENCH, 2*HH, BWCMB, 3*HH, EW, HH, TSRC*BB, 2*HH, nullptr, nullptr, nullptr);
    ewt_k<<<dim3(32, 2, 64), 256>>>(EWT, EW);

    // fused decoder scan
    dec_fused<<<512, 128>>>(YW, H0, C0, ACAT, PART, BWCAT, BWCMB + 2048,
                            ENCP, EWT, ALPHA, lens, OUTS);

    // vocab (bf16 MMA + fused chunk stats)
    bgemm<true><<<dim3(250, 32), 256>>>(OUTS, HH, BWVOC, HH, nullptr, 0, TD*BB, HH, nullptr, PMAX, PSUM);
    lse_k<<<1008, 128>>>(PMAX, PSUM, LSE, TD*BB);
    gold_k<<<1008, 128>>>(OUTS, BWVOC, tgt_pad, GOLD, TD*BB);
    final_k<<<1, 64>>>(GOLD, LSE, tgt_pad, out);
}